// round 11
// baseline (speedup 1.0000x reference)
#include <cuda_runtime.h>
#include <math.h>
#include <stdint.h>

#define NMAX 50000
#define EMAX 800000
#define CDIM 128

// ---------------- device scratch ----------------
__device__ int   g_is64;
__device__ float g_y  [(size_t)NMAX * CDIM];   // y = x@WfX + bf + pos·Wf_rel  (per-source)
__device__ float g_mx [(size_t)NMAX * CDIM];   // segmented max of y (raw, -inf if empty)
__device__ float g_delta[(size_t)NMAX * 3];
__device__ int   g_src [EMAX];
__device__ int   g_dst [EMAX];
__device__ int   g_esrc[EMAX];
__device__ int   g_cnt [NMAX];
__device__ int   g_cur [NMAX];
__device__ int   g_off [NMAX + 1];
__device__ int   g_bsum[64];
__device__ int   g_bpre[64];
// weights pre-split bf16 hi/lo in mma fragment order: 0=Wh1 1=WfX 2=Wg1 3=Wg2
__device__ unsigned int g_bfh[4][8192];
__device__ unsigned int g_bfl[4][8192];

// ---------------- helpers ----------------
__device__ __forceinline__ float lrelu(float v) { return (v > 0.f) ? v : 0.01f * v; }
__device__ __forceinline__ unsigned int pack_bf2(float e0, float e1) {
    unsigned int r;
    asm("cvt.rn.bf16x2.f32 %0, %1, %2;" : "=r"(r) : "f"(e1), "f"(e0));
    return r;
}
__device__ __forceinline__ void mma_bf16(float acc[4],
                                         unsigned int a0, unsigned int a1, unsigned int a2, unsigned int a3,
                                         unsigned int b0, unsigned int b1) {
    asm("mma.sync.aligned.m16n8k16.row.col.f32.bf16.bf16.f32 "
        "{%0,%1,%2,%3}, {%4,%5,%6,%7}, {%8,%9}, {%0,%1,%2,%3};"
        : "+f"(acc[0]), "+f"(acc[1]), "+f"(acc[2]), "+f"(acc[3])
        : "r"(a0), "r"(a1), "r"(a2), "r"(a3), "r"(b0), "r"(b1));
}

// ---------------- dtype detection ----------------
__global__ void detect_kernel(const unsigned int* __restrict__ w, int E) {
    int nz = 0;
    int lim = 2 * E;
    for (int i = threadIdx.x; i < 256; i += 32) {
        int wi = 2 * i + 1;
        if (wi < lim) nz |= (w[wi] != 0u);
    }
    nz = __any_sync(0xffffffffu, nz);
    if (threadIdx.x == 0) g_is64 = nz ? 0 : 1;
}

__global__ void zero_cnt_kernel(int n) {
    int i = blockIdx.x * blockDim.x + threadIdx.x;
    if (i < n) { g_cnt[i] = 0; g_cur[i] = 0; }
}

__global__ void convert_hist_kernel(const void* __restrict__ ei, int E) {
    int i = blockIdx.x * blockDim.x + threadIdx.x;
    if (i >= E) return;
    int s, d;
    if (g_is64) {
        const long long* p = (const long long*)ei;
        s = (int)p[i];
        d = (int)p[E + i];
    } else {
        const int* p = (const int*)ei;
        s = p[i];
        d = p[E + i];
    }
    g_src[i] = s;
    g_dst[i] = d;
    atomicAdd(&g_cnt[d], 1);
}

// ---------------- hierarchical scan ----------------
__global__ void scanA_kernel(int n) {
    __shared__ int wsum[32];
    int tid = threadIdx.x, lane = tid & 31, wid = tid >> 5;
    int i = blockIdx.x * 1024 + tid;
    int v = (i < n) ? g_cnt[i] : 0;
    int x = v;
    #pragma unroll
    for (int d = 1; d < 32; d <<= 1) {
        int t = __shfl_up_sync(0xffffffffu, x, d);
        if (lane >= d) x += t;
    }
    if (lane == 31) wsum[wid] = x;
    __syncthreads();
    if (wid == 0) {
        int s = wsum[lane];
        #pragma unroll
        for (int d = 1; d < 32; d <<= 1) {
            int t = __shfl_up_sync(0xffffffffu, s, d);
            if (lane >= d) s += t;
        }
        wsum[lane] = s;
    }
    __syncthreads();
    if (wid > 0) x += wsum[wid - 1];
    if (i < n) g_off[i + 1] = x;
    if (tid == 1023) g_bsum[blockIdx.x] = x;
}

__global__ void scanB_kernel(int nb) {
    __shared__ int ws[2];
    int t = threadIdx.x, lane = t & 31, w = t >> 5;
    int v = (t < nb) ? g_bsum[t] : 0;
    int x = v;
    #pragma unroll
    for (int d = 1; d < 32; d <<= 1) {
        int u = __shfl_up_sync(0xffffffffu, x, d);
        if (lane >= d) x += u;
    }
    if (lane == 31) ws[w] = x;
    __syncthreads();
    if (w == 1) x += ws[0];
    if (t < nb) g_bpre[t] = x - v;
}

__global__ void scanC_kernel(int n) {
    int i = blockIdx.x * 1024 + threadIdx.x;
    int add = g_bpre[blockIdx.x];
    if (i < n) g_off[i + 1] += add;
    if (i == 0) g_off[0] = 0;
}

__global__ void scatter_kernel(int E) {
    int i = blockIdx.x * blockDim.x + threadIdx.x;
    if (i >= E) return;
    int d = g_dst[i];
    int p = g_off[d] + atomicAdd(&g_cur[d], 1);
    g_esrc[p] = g_src[i];
}

// ---------------- weight prep: split bf16 hi/lo into mma fragment order ----------------
__global__ void prep_w_kernel(const float* __restrict__ Wh1, const float* __restrict__ WfX,
                              const float* __restrict__ Wg1, const float* __restrict__ Wg2) {
    const float* W = (blockIdx.y == 0) ? Wh1 : (blockIdx.y == 1) ? WfX :
                     (blockIdx.y == 2) ? Wg1 : Wg2;
    int idx = blockIdx.x * 256 + threadIdx.x;
    if (idx >= 4096) return;
    int t  = idx & 31;
    int j  = (idx >> 5) & 15;
    int ks = idx >> 9;
    int n  = j * 8 + (t >> 2);
    int k1 = ks * 16 + 2 * (t & 3);
    float w00 = W[k1 * 128 + n],       w01 = W[(k1 + 1) * 128 + n];
    float w10 = W[(k1 + 8) * 128 + n], w11 = W[(k1 + 9) * 128 + n];
    unsigned int h0 = pack_bf2(w00, w01);
    unsigned int h1 = pack_bf2(w10, w11);
    float hf00 = __uint_as_float(h0 << 16);
    float hf01 = __uint_as_float(h0 & 0xFFFF0000u);
    float hf10 = __uint_as_float(h1 << 16);
    float hf11 = __uint_as_float(h1 & 0xFFFF0000u);
    unsigned int l0 = pack_bf2(w00 - hf00, w01 - hf01);
    unsigned int l1 = pack_bf2(w10 - hf10, w11 - hf11);
    g_bfh[blockIdx.y][idx * 2 + 0] = h0;
    g_bfh[blockIdx.y][idx * 2 + 1] = h1;
    g_bfl[blockIdx.y][idx * 2 + 0] = l0;
    g_bfl[blockIdx.y][idx * 2 + 1] = l1;
}

// ---------------- shared mma building blocks ----------------
#define APITCH 272

__device__ __forceinline__ void stage_A_split(const float* __restrict__ A, int row0, int M,
                                              char* Ah, char* Al, int tid) {
    #pragma unroll
    for (int it = 0; it < 16; it++) {
        int idx = it * 256 + tid;
        int r  = idx >> 5;
        int c4 = (idx & 31) * 4;
        float4 v = make_float4(0.f, 0.f, 0.f, 0.f);
        if (row0 + r < M) v = *(const float4*)&A[(size_t)(row0 + r) * 128 + c4];
        unsigned int h01 = pack_bf2(v.x, v.y);
        unsigned int h23 = pack_bf2(v.z, v.w);
        float hf0 = __uint_as_float(h01 << 16);
        float hf1 = __uint_as_float(h01 & 0xFFFF0000u);
        float hf2 = __uint_as_float(h23 << 16);
        float hf3 = __uint_as_float(h23 & 0xFFFF0000u);
        unsigned int l01 = pack_bf2(v.x - hf0, v.y - hf1);
        unsigned int l23 = pack_bf2(v.z - hf2, v.w - hf3);
        *(uint2*)(Ah + r * APITCH + c4 * 2) = make_uint2(h01, h23);
        *(uint2*)(Al + r * APITCH + c4 * 2) = make_uint2(l01, l23);
    }
}

__device__ __forceinline__ void stage_B(const unsigned int* __restrict__ fh,
                                        const unsigned int* __restrict__ fl,
                                        unsigned int* Bh, unsigned int* Bl, int tid) {
    #pragma unroll
    for (int i = 0; i < 8; i++) {
        int idx = i * 256 + tid;
        ((uint4*)Bh)[idx] = ((const uint4*)fh)[idx];
        ((uint4*)Bl)[idx] = ((const uint4*)fl)[idx];
    }
}

__device__ __forceinline__ void mma_mainloop(const char* Ah, const char* Al,
                                             const unsigned int* Bh, const unsigned int* Bl,
                                             float acc[16][4], int lane, int warp) {
    int gr  = lane >> 2;
    int cc2 = (lane & 3) * 2;
    int abase = (warp * 16 + gr) * APITCH + cc2 * 2;
    #pragma unroll
    for (int ks = 0; ks < 8; ks++) {
        int ao = abase + ks * 32;
        unsigned int ah0 = *(const unsigned int*)(Ah + ao);
        unsigned int ah1 = *(const unsigned int*)(Ah + ao + 8 * APITCH);
        unsigned int ah2 = *(const unsigned int*)(Ah + ao + 16);
        unsigned int ah3 = *(const unsigned int*)(Ah + ao + 8 * APITCH + 16);
        unsigned int al0 = *(const unsigned int*)(Al + ao);
        unsigned int al1 = *(const unsigned int*)(Al + ao + 8 * APITCH);
        unsigned int al2 = *(const unsigned int*)(Al + ao + 16);
        unsigned int al3 = *(const unsigned int*)(Al + ao + 8 * APITCH + 16);
        #pragma unroll
        for (int jb = 0; jb < 4; jb++) {
            unsigned int bh[4][2], bl[4][2];
            #pragma unroll
            for (int q = 0; q < 4; q++) {
                int slot = ((ks * 16 + jb * 4 + q) * 32 + lane) * 2;
                uint2 t1 = *(const uint2*)&Bh[slot];
                uint2 t2 = *(const uint2*)&Bl[slot];
                bh[q][0] = t1.x; bh[q][1] = t1.y;
                bl[q][0] = t2.x; bl[q][1] = t2.y;
            }
            #pragma unroll
            for (int q = 0; q < 4; q++)
                mma_bf16(acc[jb * 4 + q], ah0, ah1, ah2, ah3, bh[q][0], bh[q][1]);
            #pragma unroll
            for (int q = 0; q < 4; q++)
                mma_bf16(acc[jb * 4 + q], ah0, ah1, ah2, ah3, bl[q][0], bl[q][1]);
            #pragma unroll
            for (int q = 0; q < 4; q++)
                mma_bf16(acc[jb * 4 + q], al0, al1, al2, al3, bh[q][0], bh[q][1]);
        }
    }
}

// ---------------- y = x @ WfX + bf + pos·Wf_rel ----------------
#define MMA_SMEM_XF (32768 * 2 + 34816 * 2 + 512 + 1536)
__global__ __launch_bounds__(256, 1)
void xf_mma_kernel(const float* __restrict__ A, const float* __restrict__ bias,
                   const float* __restrict__ pos, const float* __restrict__ Wf,
                   float* __restrict__ O, int M) {
    extern __shared__ char smx[];
    unsigned int* Bh = (unsigned int*)smx;
    unsigned int* Bl = (unsigned int*)(smx + 32768);
    char* Ah = smx + 65536;
    char* Al = smx + 65536 + 34816;
    float* sbias = (float*)(smx + 65536 + 69632);
    float* sWf   = (float*)(smx + 65536 + 69632 + 512);   // Wf rel rows [3][128]
    int tid = threadIdx.x, lane = tid & 31, warp = tid >> 5;
    int row0 = blockIdx.x * 128;

    stage_B(g_bfh[1], g_bfl[1], Bh, Bl, tid);
    if (tid < 128) sbias[tid] = bias[tid];
    if (tid >= 128 && tid < 224) *(float4*)&sWf[(tid - 128) * 4] = *(const float4*)&Wf[(tid - 128) * 4];
    stage_A_split(A, row0, M, Ah, Al, tid);
    __syncthreads();

    float acc[16][4];
    #pragma unroll
    for (int j = 0; j < 16; j++)
        #pragma unroll
        for (int q = 0; q < 4; q++) acc[j][q] = 0.f;

    mma_mainloop(Ah, Al, Bh, Bl, acc, lane, warp);

    int gr  = lane >> 2;
    int cc2 = (lane & 3) * 2;
    int r1 = row0 + warp * 16 + gr;
    float pAx = 0.f, pAy = 0.f, pAz = 0.f, pBx = 0.f, pBy = 0.f, pBz = 0.f;
    if (r1 < M)     { pAx = pos[r1 * 3]; pAy = pos[r1 * 3 + 1]; pAz = pos[r1 * 3 + 2]; }
    if (r1 + 8 < M) { pBx = pos[(r1 + 8) * 3]; pBy = pos[(r1 + 8) * 3 + 1]; pBz = pos[(r1 + 8) * 3 + 2]; }
    #pragma unroll
    for (int j = 0; j < 16; j++) {
        int col = j * 8 + cc2;
        float b0 = sbias[col], b1 = sbias[col + 1];
        float w00 = sWf[col], w10 = sWf[128 + col], w20 = sWf[256 + col];
        float w01 = sWf[col + 1], w11 = sWf[128 + col + 1], w21 = sWf[256 + col + 1];
        if (r1 < M) {
            float y0 = acc[j][0] + b0 + pAx * w00 + pAy * w10 + pAz * w20;
            float y1 = acc[j][1] + b1 + pAx * w01 + pAy * w11 + pAz * w21;
            *(float2*)&O[(size_t)r1 * 128 + col] = make_float2(y0, y1);
        }
        if (r1 + 8 < M) {
            float y2 = acc[j][2] + b0 + pBx * w00 + pBy * w10 + pBz * w20;
            float y3 = acc[j][3] + b1 + pBx * w01 + pBy * w11 + pBz * w21;
            *(float2*)&O[(size_t)(r1 + 8) * 128 + col] = make_float2(y2, y3);
        }
    }
}

// ---------------- delta = tanh(lrelu(x@Wh1+bh1) @ Wh2 + bh2) ----------------
#define MMA_SMEM_H (32768 * 2 + 34816 * 2 + 512 + 1536)
__global__ __launch_bounds__(256, 1)
void hdelta_mma_kernel(const float* __restrict__ A, const float* __restrict__ bias,
                       const float* __restrict__ Wh2, const float* __restrict__ bh2, int M) {
    extern __shared__ char smx[];
    unsigned int* Bh = (unsigned int*)smx;
    unsigned int* Bl = (unsigned int*)(smx + 32768);
    char* Ah = smx + 65536;
    char* Al = smx + 65536 + 34816;
    float* sbias = (float*)(smx + 65536 + 69632);
    float* sW2   = (float*)(smx + 65536 + 69632 + 512);
    int tid = threadIdx.x, lane = tid & 31, warp = tid >> 5;
    int row0 = blockIdx.x * 128;

    stage_B(g_bfh[0], g_bfl[0], Bh, Bl, tid);
    if (tid < 128) sbias[tid] = bias[tid];
    if (tid >= 128 && tid < 224) *(float4*)&sW2[(tid - 128) * 4] = *(const float4*)&Wh2[(tid - 128) * 4];
    stage_A_split(A, row0, M, Ah, Al, tid);
    __syncthreads();

    float acc[16][4];
    #pragma unroll
    for (int j = 0; j < 16; j++)
        #pragma unroll
        for (int q = 0; q < 4; q++) acc[j][q] = 0.f;

    mma_mainloop(Ah, Al, Bh, Bl, acc, lane, warp);

    int gr  = lane >> 2;
    int cc2 = (lane & 3) * 2;
    float pA0 = 0.f, pA1 = 0.f, pA2 = 0.f;
    float pB0 = 0.f, pB1 = 0.f, pB2 = 0.f;
    #pragma unroll
    for (int j = 0; j < 16; j++) {
        int col = j * 8 + cc2;
        float b0 = sbias[col], b1 = sbias[col + 1];
        float v0 = lrelu(acc[j][0] + b0);
        float v1 = lrelu(acc[j][1] + b1);
        float v2 = lrelu(acc[j][2] + b0);
        float v3 = lrelu(acc[j][3] + b1);
        float w00 = sW2[col * 3 + 0], w01 = sW2[col * 3 + 1], w02 = sW2[col * 3 + 2];
        float w10 = sW2[(col + 1) * 3 + 0], w11 = sW2[(col + 1) * 3 + 1], w12 = sW2[(col + 1) * 3 + 2];
        pA0 += v0 * w00 + v1 * w10;
        pA1 += v0 * w01 + v1 * w11;
        pA2 += v0 * w02 + v1 * w12;
        pB0 += v2 * w00 + v3 * w10;
        pB1 += v2 * w01 + v3 * w11;
        pB2 += v2 * w02 + v3 * w12;
    }
    #pragma unroll
    for (int d = 1; d < 4; d <<= 1) {
        pA0 += __shfl_xor_sync(0xffffffffu, pA0, d);
        pA1 += __shfl_xor_sync(0xffffffffu, pA1, d);
        pA2 += __shfl_xor_sync(0xffffffffu, pA2, d);
        pB0 += __shfl_xor_sync(0xffffffffu, pB0, d);
        pB1 += __shfl_xor_sync(0xffffffffu, pB1, d);
        pB2 += __shfl_xor_sync(0xffffffffu, pB2, d);
    }
    if ((lane & 3) == 0) {
        int r1 = row0 + warp * 16 + gr;
        float c0 = bh2[0], c1 = bh2[1], c2 = bh2[2];
        if (r1 < M) {
            g_delta[r1 * 3 + 0] = tanhf(pA0 + c0);
            g_delta[r1 * 3 + 1] = tanhf(pA1 + c1);
            g_delta[r1 * 3 + 2] = tanhf(pA2 + c2);
        }
        if (r1 + 8 < M) {
            g_delta[(r1 + 8) * 3 + 0] = tanhf(pB0 + c0);
            g_delta[(r1 + 8) * 3 + 1] = tanhf(pB1 + c1);
            g_delta[(r1 + 8) * 3 + 2] = tanhf(pB2 + c2);
        }
    }
}

// ---------------- agg: pure segmented max-gather of y (raw max, -inf if empty) ----------------
__global__ void agg_kernel(int N) {
    int warp = (blockIdx.x * blockDim.x + threadIdx.x) >> 5;
    int lane = threadIdx.x & 31;
    if (warp >= N) return;
    int c = lane * 4;
    int p0 = g_off[warp], p1 = g_off[warp + 1];
    float4 acc = make_float4(-INFINITY, -INFINITY, -INFINITY, -INFINITY);
    int p = p0;
    for (; p + 4 <= p1; p += 4) {
        int s0 = g_esrc[p + 0];
        int s1 = g_esrc[p + 1];
        int s2 = g_esrc[p + 2];
        int s3 = g_esrc[p + 3];
        float4 v0 = *(const float4*)&g_y[(size_t)s0 * 128 + c];
        float4 v1 = *(const float4*)&g_y[(size_t)s1 * 128 + c];
        float4 v2 = *(const float4*)&g_y[(size_t)s2 * 128 + c];
        float4 v3 = *(const float4*)&g_y[(size_t)s3 * 128 + c];
        acc.x = fmaxf(fmaxf(fmaxf(acc.x, v0.x), fmaxf(v1.x, v2.x)), v3.x);
        acc.y = fmaxf(fmaxf(fmaxf(acc.y, v0.y), fmaxf(v1.y, v2.y)), v3.y);
        acc.z = fmaxf(fmaxf(fmaxf(acc.z, v0.z), fmaxf(v1.z, v2.z)), v3.z);
        acc.w = fmaxf(fmaxf(fmaxf(acc.w, v0.w), fmaxf(v1.w, v2.w)), v3.w);
    }
    for (; p < p1; ++p) {
        int s = g_esrc[p];
        float4 v = *(const float4*)&g_y[(size_t)s * 128 + c];
        acc.x = fmaxf(acc.x, v.x);
        acc.y = fmaxf(acc.y, v.y);
        acc.z = fmaxf(acc.z, v.z);
        acc.w = fmaxf(acc.w, v.w);
    }
    *(float4*)&g_mx[(size_t)warp * 128 + c] = acc;
}

// ---------------- out = lrelu(agg@Wg1+bg1)@Wg2 + bg2 + x ----------------
// A-staging computes agg = lrelu(mx + c_d) with c_d = (delta_d - pos_d)·Wf_rel; empty -> 0.
#define MMA_SMEM_O (32768 * 2 + 34816 * 2 + 512 + 512 + 1536)
__global__ __launch_bounds__(256, 1)
void out_mma_kernel(const float* __restrict__ b1, const float* __restrict__ b2,
                    const float* __restrict__ X, const float* __restrict__ pos,
                    const float* __restrict__ Wf, float* __restrict__ O, int M) {
    extern __shared__ char smx[];
    unsigned int* Bh = (unsigned int*)smx;
    unsigned int* Bl = (unsigned int*)(smx + 32768);
    char* Ah = smx + 65536;
    char* Al = smx + 65536 + 34816;
    float* sb1 = (float*)(smx + 65536 + 69632);
    float* sb2 = (float*)(smx + 65536 + 69632 + 512);
    float* sWf = (float*)(smx + 65536 + 69632 + 1024);
    int tid = threadIdx.x, lane = tid & 31, warp = tid >> 5;
    int row0 = blockIdx.x * 128;
    int gr  = lane >> 2;
    int cc2 = (lane & 3) * 2;

    stage_B(g_bfh[2], g_bfl[2], Bh, Bl, tid);
    if (tid < 128) sb1[tid] = b1[tid];
    else if (tid < 256) sb2[tid - 128] = b2[tid - 128];
    if (tid < 96) *(float4*)&sWf[tid * 4] = *(const float4*)&Wf[tid * 4];
    __syncthreads();   // sWf needed by A staging below

    // stage A = lrelu(mx + c_d), split hi/lo
    #pragma unroll
    for (int it = 0; it < 16; it++) {
        int idx = it * 256 + tid;
        int r  = idx >> 5;
        int c4 = (idx & 31) * 4;
        int row = row0 + r;
        float4 v = make_float4(0.f, 0.f, 0.f, 0.f);
        if (row < M) {
            float4 t = *(const float4*)&g_mx[(size_t)row * 128 + c4];
            float dx = g_delta[row * 3 + 0] - pos[row * 3 + 0];
            float dy = g_delta[row * 3 + 1] - pos[row * 3 + 1];
            float dz = g_delta[row * 3 + 2] - pos[row * 3 + 2];
            float c0 = dx * sWf[c4 + 0] + dy * sWf[128 + c4 + 0] + dz * sWf[256 + c4 + 0];
            float c1 = dx * sWf[c4 + 1] + dy * sWf[128 + c4 + 1] + dz * sWf[256 + c4 + 1];
            float c2 = dx * sWf[c4 + 2] + dy * sWf[128 + c4 + 2] + dz * sWf[256 + c4 + 2];
            float c3 = dx * sWf[c4 + 3] + dy * sWf[128 + c4 + 3] + dz * sWf[256 + c4 + 3];
            v.x = (t.x == -INFINITY) ? 0.f : lrelu(t.x + c0);
            v.y = (t.y == -INFINITY) ? 0.f : lrelu(t.y + c1);
            v.z = (t.z == -INFINITY) ? 0.f : lrelu(t.z + c2);
            v.w = (t.w == -INFINITY) ? 0.f : lrelu(t.w + c3);
        }
        unsigned int h01 = pack_bf2(v.x, v.y);
        unsigned int h23 = pack_bf2(v.z, v.w);
        float hf0 = __uint_as_float(h01 << 16);
        float hf1 = __uint_as_float(h01 & 0xFFFF0000u);
        float hf2 = __uint_as_float(h23 << 16);
        float hf3 = __uint_as_float(h23 & 0xFFFF0000u);
        unsigned int l01 = pack_bf2(v.x - hf0, v.y - hf1);
        unsigned int l23 = pack_bf2(v.z - hf2, v.w - hf3);
        *(uint2*)(Ah + r * APITCH + c4 * 2) = make_uint2(h01, h23);
        *(uint2*)(Al + r * APITCH + c4 * 2) = make_uint2(l01, l23);
    }
    __syncthreads();

    float acc[16][4];
    #pragma unroll
    for (int j = 0; j < 16; j++)
        #pragma unroll
        for (int q = 0; q < 4; q++) acc[j][q] = 0.f;

    mma_mainloop(Ah, Al, Bh, Bl, acc, lane, warp);
    __syncthreads();

    // t = lrelu(acc + bg1) back into A tiles; restage B = Wg2
    {
        int rlA = warp * 16 + gr;
        #pragma unroll
        for (int j = 0; j < 16; j++) {
            int col = j * 8 + cc2;
            float b0 = sb1[col], b1v = sb1[col + 1];
            float v0 = lrelu(acc[j][0] + b0);
            float v1 = lrelu(acc[j][1] + b1v);
            float v2 = lrelu(acc[j][2] + b0);
            float v3 = lrelu(acc[j][3] + b1v);
            unsigned int hA = pack_bf2(v0, v1);
            unsigned int hB = pack_bf2(v2, v3);
            float hf0 = __uint_as_float(hA << 16);
            float hf1 = __uint_as_float(hA & 0xFFFF0000u);
            float hf2 = __uint_as_float(hB << 16);
            float hf3 = __uint_as_float(hB & 0xFFFF0000u);
            unsigned int lA = pack_bf2(v0 - hf0, v1 - hf1);
            unsigned int lB = pack_bf2(v2 - hf2, v3 - hf3);
            *(unsigned int*)(Ah + rlA * APITCH + col * 2) = hA;
            *(unsigned int*)(Al + rlA * APITCH + col * 2) = lA;
            *(unsigned int*)(Ah + (rlA + 8) * APITCH + col * 2) = hB;
            *(unsigned int*)(Al + (rlA + 8) * APITCH + col * 2) = lB;
        }
    }
    stage_B(g_bfh[3], g_bfl[3], Bh, Bl, tid);
    __syncthreads();

    #pragma unroll
    for (int j = 0; j < 16; j++)
        #pragma unroll
        for (int q = 0; q < 4; q++) acc[j][q] = 0.f;

    mma_mainloop(Ah, Al, Bh, Bl, acc, lane, warp);

    int r1 = row0 + warp * 16 + gr;
    #pragma unroll
    for (int j = 0; j < 16; j++) {
        int col = j * 8 + cc2;
        float b0 = sb2[col], b1v = sb2[col + 1];
        if (r1 < M) {
            float2 rx = *(const float2*)&X[(size_t)r1 * 128 + col];
            *(float2*)&O[(size_t)r1 * 128 + col] =
                make_float2(acc[j][0] + b0 + rx.x, acc[j][1] + b1v + rx.y);
        }
        if (r1 + 8 < M) {
            float2 rx = *(const float2*)&X[(size_t)(r1 + 8) * 128 + col];
            *(float2*)&O[(size_t)(r1 + 8) * 128 + col] =
                make_float2(acc[j][2] + b0 + rx.x, acc[j][3] + b1v + rx.y);
        }
    }
}

// ---------------- launch ----------------
extern "C" void kernel_launch(void* const* d_in, const int* in_sizes, int n_in,
                              void* d_out, int out_size) {
    const float* x   = (const float*)d_in[0];
    const float* pos = (const float*)d_in[1];
    const void*  ei  = d_in[2];
    const float* Wh1 = (const float*)d_in[3];
    const float* bh1 = (const float*)d_in[4];
    const float* Wh2 = (const float*)d_in[5];
    const float* bh2 = (const float*)d_in[6];
    const float* Wf  = (const float*)d_in[7];
    const float* bf  = (const float*)d_in[8];
    const float* Wg1 = (const float*)d_in[9];
    const float* bg1 = (const float*)d_in[10];
    const float* Wg2 = (const float*)d_in[11];
    const float* bg2 = (const float*)d_in[12];
    float* out = (float*)d_out;

    int M = in_sizes[0] / CDIM;   // 50000
    int E = in_sizes[2] / 2;      // 800000

    cudaFuncSetAttribute(xf_mma_kernel,     cudaFuncAttributeMaxDynamicSharedMemorySize, MMA_SMEM_XF);
    cudaFuncSetAttribute(hdelta_mma_kernel, cudaFuncAttributeMaxDynamicSharedMemorySize, MMA_SMEM_H);
    cudaFuncSetAttribute(out_mma_kernel,    cudaFuncAttributeMaxDynamicSharedMemorySize, MMA_SMEM_O);

    float* yp;
    cudaGetSymbolAddress((void**)&yp, g_y);

    int gemm_blocks = (M + 127) / 128;
    int eblocks = (E + 255) / 256;
    int nblocks = (M + 255) / 256;
    int sblocks = (M + 1023) / 1024;
    int wblocks = (M + 7) / 8;

    static cudaStream_t s_csr = nullptr, s_h = nullptr;
    static cudaEvent_t  s_e0 = nullptr, s_e1 = nullptr, s_e2 = nullptr;
    if (s_csr == nullptr) {
        cudaStreamCreateWithFlags(&s_csr, cudaStreamNonBlocking);
        cudaStreamCreateWithFlags(&s_h,   cudaStreamNonBlocking);
        cudaEventCreateWithFlags(&s_e0, cudaEventDisableTiming);
        cudaEventCreateWithFlags(&s_e1, cudaEventDisableTiming);
        cudaEventCreateWithFlags(&s_e2, cudaEventDisableTiming);
    }

    // main: weight prep
    prep_w_kernel<<<dim3(16, 4), 256>>>(Wh1, Wf + 3 * 128, Wg1, Wg2);
    cudaEventRecord(s_e0, 0);

    // branch 1: CSR build
    cudaStreamWaitEvent(s_csr, s_e0, 0);
    detect_kernel<<<1, 32, 0, s_csr>>>((const unsigned int*)ei, E);
    zero_cnt_kernel<<<nblocks, 256, 0, s_csr>>>(M);
    convert_hist_kernel<<<eblocks, 256, 0, s_csr>>>(ei, E);
    scanA_kernel<<<sblocks, 1024, 0, s_csr>>>(M);
    scanB_kernel<<<1, 64, 0, s_csr>>>(sblocks);
    scanC_kernel<<<sblocks, 1024, 0, s_csr>>>(M);
    scatter_kernel<<<eblocks, 256, 0, s_csr>>>(E);
    cudaEventRecord(s_e1, s_csr);

    // branch 2: hdelta (independent of CSR and agg; overlaps xf+agg)
    cudaStreamWaitEvent(s_h, s_e0, 0);
    hdelta_mma_kernel<<<gemm_blocks, 256, MMA_SMEM_H, s_h>>>(x, bh1, Wh2, bh2, M);
    cudaEventRecord(s_e2, s_h);

    // main: y GEMM, then max-gather (needs CSR), then out (needs delta)
    xf_mma_kernel<<<gemm_blocks, 256, MMA_SMEM_XF>>>(x, bf, pos, Wf, yp, M);
    cudaStreamWaitEvent(0, s_e1, 0);
    agg_kernel<<<wblocks, 256>>>(M);
    cudaStreamWaitEvent(0, s_e2, 0);
    out_mma_kernel<<<gemm_blocks, 256, MMA_SMEM_O>>>(bg1, bg2, x, pos, Wf, out, M);
}

// round 12
// speedup vs baseline: 1.0398x; 1.0398x over previous
#include <cuda_runtime.h>
#include <math.h>
#include <stdint.h>

#define NMAX 50000
#define EMAX 800000
#define CDIM 128

// ---------------- device scratch ----------------
__device__ int   g_is64;
__device__ float g_y  [(size_t)NMAX * CDIM];   // y = x@WfX + bf + pos·Wf_rel  (per-source)
__device__ float g_mx [(size_t)NMAX * CDIM];   // segmented max of y (raw, -inf if empty)
__device__ float g_delta[(size_t)NMAX * 3];
__device__ int   g_src [EMAX];
__device__ int   g_dst [EMAX];
__device__ int   g_esrc[EMAX];
__device__ int   g_cnt [NMAX];
__device__ int   g_cur [NMAX];
__device__ int   g_off [NMAX + 1];
__device__ int   g_bsum[64];
__device__ int   g_bpre[64];
// weights pre-split bf16 hi/lo in mma fragment order: 0=Wh1 1=WfX 2=Wg1 3=Wg2
__device__ unsigned int g_bfh[4][8192];
__device__ unsigned int g_bfl[4][8192];

// ---------------- helpers ----------------
__device__ __forceinline__ float lrelu(float v) { return (v > 0.f) ? v : 0.01f * v; }
__device__ __forceinline__ unsigned int pack_bf2(float e0, float e1) {
    unsigned int r;
    asm("cvt.rn.bf16x2.f32 %0, %1, %2;" : "=r"(r) : "f"(e1), "f"(e0));
    return r;
}
__device__ __forceinline__ void mma_bf16(float acc[4],
                                         unsigned int a0, unsigned int a1, unsigned int a2, unsigned int a3,
                                         unsigned int b0, unsigned int b1) {
    asm("mma.sync.aligned.m16n8k16.row.col.f32.bf16.bf16.f32 "
        "{%0,%1,%2,%3}, {%4,%5,%6,%7}, {%8,%9}, {%0,%1,%2,%3};"
        : "+f"(acc[0]), "+f"(acc[1]), "+f"(acc[2]), "+f"(acc[3])
        : "r"(a0), "r"(a1), "r"(a2), "r"(a3), "r"(b0), "r"(b1));
}

// ---------------- dtype detection ----------------
__global__ void detect_kernel(const unsigned int* __restrict__ w, int E) {
    int nz = 0;
    int lim = 2 * E;
    for (int i = threadIdx.x; i < 256; i += 32) {
        int wi = 2 * i + 1;
        if (wi < lim) nz |= (w[wi] != 0u);
    }
    nz = __any_sync(0xffffffffu, nz);
    if (threadIdx.x == 0) g_is64 = nz ? 0 : 1;
}

__global__ void zero_cnt_kernel(int n) {
    int i = blockIdx.x * blockDim.x + threadIdx.x;
    if (i < n) { g_cnt[i] = 0; g_cur[i] = 0; }
}

__global__ void convert_hist_kernel(const void* __restrict__ ei, int E) {
    int i = blockIdx.x * blockDim.x + threadIdx.x;
    if (i >= E) return;
    int s, d;
    if (g_is64) {
        const long long* p = (const long long*)ei;
        s = (int)p[i];
        d = (int)p[E + i];
    } else {
        const int* p = (const int*)ei;
        s = p[i];
        d = p[E + i];
    }
    g_src[i] = s;
    g_dst[i] = d;
    atomicAdd(&g_cnt[d], 1);
}

// ---------------- hierarchical scan ----------------
__global__ void scanA_kernel(int n) {
    __shared__ int wsum[32];
    int tid = threadIdx.x, lane = tid & 31, wid = tid >> 5;
    int i = blockIdx.x * 1024 + tid;
    int v = (i < n) ? g_cnt[i] : 0;
    int x = v;
    #pragma unroll
    for (int d = 1; d < 32; d <<= 1) {
        int t = __shfl_up_sync(0xffffffffu, x, d);
        if (lane >= d) x += t;
    }
    if (lane == 31) wsum[wid] = x;
    __syncthreads();
    if (wid == 0) {
        int s = wsum[lane];
        #pragma unroll
        for (int d = 1; d < 32; d <<= 1) {
            int t = __shfl_up_sync(0xffffffffu, s, d);
            if (lane >= d) s += t;
        }
        wsum[lane] = s;
    }
    __syncthreads();
    if (wid > 0) x += wsum[wid - 1];
    if (i < n) g_off[i + 1] = x;
    if (tid == 1023) g_bsum[blockIdx.x] = x;
}

__global__ void scanB_kernel(int nb) {
    __shared__ int ws[2];
    int t = threadIdx.x, lane = t & 31, w = t >> 5;
    int v = (t < nb) ? g_bsum[t] : 0;
    int x = v;
    #pragma unroll
    for (int d = 1; d < 32; d <<= 1) {
        int u = __shfl_up_sync(0xffffffffu, x, d);
        if (lane >= d) x += u;
    }
    if (lane == 31) ws[w] = x;
    __syncthreads();
    if (w == 1) x += ws[0];
    if (t < nb) g_bpre[t] = x - v;
}

__global__ void scanC_kernel(int n) {
    int i = blockIdx.x * 1024 + threadIdx.x;
    int add = g_bpre[blockIdx.x];
    if (i < n) g_off[i + 1] += add;
    if (i == 0) g_off[0] = 0;
}

__global__ void scatter_kernel(int E) {
    int i = blockIdx.x * blockDim.x + threadIdx.x;
    if (i >= E) return;
    int d = g_dst[i];
    int p = g_off[d] + atomicAdd(&g_cur[d], 1);
    g_esrc[p] = g_src[i];
}

// ---------------- weight prep: split bf16 hi/lo into mma fragment order ----------------
__global__ void prep_w_kernel(const float* __restrict__ Wh1, const float* __restrict__ WfX,
                              const float* __restrict__ Wg1, const float* __restrict__ Wg2) {
    const float* W = (blockIdx.y == 0) ? Wh1 : (blockIdx.y == 1) ? WfX :
                     (blockIdx.y == 2) ? Wg1 : Wg2;
    int idx = blockIdx.x * 256 + threadIdx.x;
    if (idx >= 4096) return;
    int t  = idx & 31;
    int j  = (idx >> 5) & 15;
    int ks = idx >> 9;
    int n  = j * 8 + (t >> 2);
    int k1 = ks * 16 + 2 * (t & 3);
    float w00 = W[k1 * 128 + n],       w01 = W[(k1 + 1) * 128 + n];
    float w10 = W[(k1 + 8) * 128 + n], w11 = W[(k1 + 9) * 128 + n];
    unsigned int h0 = pack_bf2(w00, w01);
    unsigned int h1 = pack_bf2(w10, w11);
    float hf00 = __uint_as_float(h0 << 16);
    float hf01 = __uint_as_float(h0 & 0xFFFF0000u);
    float hf10 = __uint_as_float(h1 << 16);
    float hf11 = __uint_as_float(h1 & 0xFFFF0000u);
    unsigned int l0 = pack_bf2(w00 - hf00, w01 - hf01);
    unsigned int l1 = pack_bf2(w10 - hf10, w11 - hf11);
    g_bfh[blockIdx.y][idx * 2 + 0] = h0;
    g_bfh[blockIdx.y][idx * 2 + 1] = h1;
    g_bfl[blockIdx.y][idx * 2 + 0] = l0;
    g_bfl[blockIdx.y][idx * 2 + 1] = l1;
}

// ---------------- shared mma building blocks ----------------
#define APITCH 272

__device__ __forceinline__ void stage_A_split(const float* __restrict__ A, int row0, int M,
                                              char* Ah, char* Al, int tid) {
    #pragma unroll
    for (int it = 0; it < 16; it++) {
        int idx = it * 256 + tid;
        int r  = idx >> 5;
        int c4 = (idx & 31) * 4;
        float4 v = make_float4(0.f, 0.f, 0.f, 0.f);
        if (row0 + r < M) v = *(const float4*)&A[(size_t)(row0 + r) * 128 + c4];
        unsigned int h01 = pack_bf2(v.x, v.y);
        unsigned int h23 = pack_bf2(v.z, v.w);
        float hf0 = __uint_as_float(h01 << 16);
        float hf1 = __uint_as_float(h01 & 0xFFFF0000u);
        float hf2 = __uint_as_float(h23 << 16);
        float hf3 = __uint_as_float(h23 & 0xFFFF0000u);
        unsigned int l01 = pack_bf2(v.x - hf0, v.y - hf1);
        unsigned int l23 = pack_bf2(v.z - hf2, v.w - hf3);
        *(uint2*)(Ah + r * APITCH + c4 * 2) = make_uint2(h01, h23);
        *(uint2*)(Al + r * APITCH + c4 * 2) = make_uint2(l01, l23);
    }
}

__device__ __forceinline__ void stage_B(const unsigned int* __restrict__ fh,
                                        const unsigned int* __restrict__ fl,
                                        unsigned int* Bh, unsigned int* Bl, int tid) {
    #pragma unroll
    for (int i = 0; i < 8; i++) {
        int idx = i * 256 + tid;
        ((uint4*)Bh)[idx] = ((const uint4*)fh)[idx];
        ((uint4*)Bl)[idx] = ((const uint4*)fl)[idx];
    }
}

__device__ __forceinline__ void mma_mainloop(const char* Ah, const char* Al,
                                             const unsigned int* Bh, const unsigned int* Bl,
                                             float acc[16][4], int lane, int warp) {
    int gr  = lane >> 2;
    int cc2 = (lane & 3) * 2;
    int abase = (warp * 16 + gr) * APITCH + cc2 * 2;
    #pragma unroll
    for (int ks = 0; ks < 8; ks++) {
        int ao = abase + ks * 32;
        unsigned int ah0 = *(const unsigned int*)(Ah + ao);
        unsigned int ah1 = *(const unsigned int*)(Ah + ao + 8 * APITCH);
        unsigned int ah2 = *(const unsigned int*)(Ah + ao + 16);
        unsigned int ah3 = *(const unsigned int*)(Ah + ao + 8 * APITCH + 16);
        unsigned int al0 = *(const unsigned int*)(Al + ao);
        unsigned int al1 = *(const unsigned int*)(Al + ao + 8 * APITCH);
        unsigned int al2 = *(const unsigned int*)(Al + ao + 16);
        unsigned int al3 = *(const unsigned int*)(Al + ao + 8 * APITCH + 16);
        #pragma unroll
        for (int jb = 0; jb < 4; jb++) {
            unsigned int bh[4][2], bl[4][2];
            #pragma unroll
            for (int q = 0; q < 4; q++) {
                int slot = ((ks * 16 + jb * 4 + q) * 32 + lane) * 2;
                uint2 t1 = *(const uint2*)&Bh[slot];
                uint2 t2 = *(const uint2*)&Bl[slot];
                bh[q][0] = t1.x; bh[q][1] = t1.y;
                bl[q][0] = t2.x; bl[q][1] = t2.y;
            }
            #pragma unroll
            for (int q = 0; q < 4; q++)
                mma_bf16(acc[jb * 4 + q], ah0, ah1, ah2, ah3, bh[q][0], bh[q][1]);
            #pragma unroll
            for (int q = 0; q < 4; q++)
                mma_bf16(acc[jb * 4 + q], ah0, ah1, ah2, ah3, bl[q][0], bl[q][1]);
            #pragma unroll
            for (int q = 0; q < 4; q++)
                mma_bf16(acc[jb * 4 + q], al0, al1, al2, al3, bh[q][0], bh[q][1]);
        }
    }
}

// ---------------- y = x @ WfX + bf + pos·Wf_rel ----------------
#define MMA_SMEM_XF (32768 * 2 + 34816 * 2 + 512 + 1536)
__global__ __launch_bounds__(256, 1)
void xf_mma_kernel(const float* __restrict__ A, const float* __restrict__ bias,
                   const float* __restrict__ pos, const float* __restrict__ Wf,
                   float* __restrict__ O, int M) {
    extern __shared__ char smx[];
    unsigned int* Bh = (unsigned int*)smx;
    unsigned int* Bl = (unsigned int*)(smx + 32768);
    char* Ah = smx + 65536;
    char* Al = smx + 65536 + 34816;
    float* sbias = (float*)(smx + 65536 + 69632);
    float* sWf   = (float*)(smx + 65536 + 69632 + 512);
    int tid = threadIdx.x, lane = tid & 31, warp = tid >> 5;
    int row0 = blockIdx.x * 128;

    stage_B(g_bfh[1], g_bfl[1], Bh, Bl, tid);
    if (tid < 128) sbias[tid] = bias[tid];
    if (tid >= 128 && tid < 224) *(float4*)&sWf[(tid - 128) * 4] = *(const float4*)&Wf[(tid - 128) * 4];
    stage_A_split(A, row0, M, Ah, Al, tid);
    __syncthreads();

    float acc[16][4];
    #pragma unroll
    for (int j = 0; j < 16; j++)
        #pragma unroll
        for (int q = 0; q < 4; q++) acc[j][q] = 0.f;

    mma_mainloop(Ah, Al, Bh, Bl, acc, lane, warp);

    int gr  = lane >> 2;
    int cc2 = (lane & 3) * 2;
    int r1 = row0 + warp * 16 + gr;
    float pAx = 0.f, pAy = 0.f, pAz = 0.f, pBx = 0.f, pBy = 0.f, pBz = 0.f;
    if (r1 < M)     { pAx = pos[r1 * 3]; pAy = pos[r1 * 3 + 1]; pAz = pos[r1 * 3 + 2]; }
    if (r1 + 8 < M) { pBx = pos[(r1 + 8) * 3]; pBy = pos[(r1 + 8) * 3 + 1]; pBz = pos[(r1 + 8) * 3 + 2]; }
    #pragma unroll
    for (int j = 0; j < 16; j++) {
        int col = j * 8 + cc2;
        float b0 = sbias[col], b1 = sbias[col + 1];
        float w00 = sWf[col], w10 = sWf[128 + col], w20 = sWf[256 + col];
        float w01 = sWf[col + 1], w11 = sWf[128 + col + 1], w21 = sWf[256 + col + 1];
        if (r1 < M) {
            float y0 = acc[j][0] + b0 + pAx * w00 + pAy * w10 + pAz * w20;
            float y1 = acc[j][1] + b1 + pAx * w01 + pAy * w11 + pAz * w21;
            *(float2*)&O[(size_t)r1 * 128 + col] = make_float2(y0, y1);
        }
        if (r1 + 8 < M) {
            float y2 = acc[j][2] + b0 + pBx * w00 + pBy * w10 + pBz * w20;
            float y3 = acc[j][3] + b1 + pBx * w01 + pBy * w11 + pBz * w21;
            *(float2*)&O[(size_t)(r1 + 8) * 128 + col] = make_float2(y2, y3);
        }
    }
}

// ---------------- delta = tanh(lrelu(x@Wh1+bh1) @ Wh2 + bh2) ----------------
#define MMA_SMEM_H (32768 * 2 + 34816 * 2 + 512 + 1536)
__global__ __launch_bounds__(256, 1)
void hdelta_mma_kernel(const float* __restrict__ A, const float* __restrict__ bias,
                       const float* __restrict__ Wh2, const float* __restrict__ bh2, int M) {
    extern __shared__ char smx[];
    unsigned int* Bh = (unsigned int*)smx;
    unsigned int* Bl = (unsigned int*)(smx + 32768);
    char* Ah = smx + 65536;
    char* Al = smx + 65536 + 34816;
    float* sbias = (float*)(smx + 65536 + 69632);
    float* sW2   = (float*)(smx + 65536 + 69632 + 512);
    int tid = threadIdx.x, lane = tid & 31, warp = tid >> 5;
    int row0 = blockIdx.x * 128;

    stage_B(g_bfh[0], g_bfl[0], Bh, Bl, tid);
    if (tid < 128) sbias[tid] = bias[tid];
    if (tid >= 128 && tid < 224) *(float4*)&sW2[(tid - 128) * 4] = *(const float4*)&Wh2[(tid - 128) * 4];
    stage_A_split(A, row0, M, Ah, Al, tid);
    __syncthreads();

    float acc[16][4];
    #pragma unroll
    for (int j = 0; j < 16; j++)
        #pragma unroll
        for (int q = 0; q < 4; q++) acc[j][q] = 0.f;

    mma_mainloop(Ah, Al, Bh, Bl, acc, lane, warp);

    int gr  = lane >> 2;
    int cc2 = (lane & 3) * 2;
    float pA0 = 0.f, pA1 = 0.f, pA2 = 0.f;
    float pB0 = 0.f, pB1 = 0.f, pB2 = 0.f;
    #pragma unroll
    for (int j = 0; j < 16; j++) {
        int col = j * 8 + cc2;
        float b0 = sbias[col], b1 = sbias[col + 1];
        float v0 = lrelu(acc[j][0] + b0);
        float v1 = lrelu(acc[j][1] + b1);
        float v2 = lrelu(acc[j][2] + b0);
        float v3 = lrelu(acc[j][3] + b1);
        float w00 = sW2[col * 3 + 0], w01 = sW2[col * 3 + 1], w02 = sW2[col * 3 + 2];
        float w10 = sW2[(col + 1) * 3 + 0], w11 = sW2[(col + 1) * 3 + 1], w12 = sW2[(col + 1) * 3 + 2];
        pA0 += v0 * w00 + v1 * w10;
        pA1 += v0 * w01 + v1 * w11;
        pA2 += v0 * w02 + v1 * w12;
        pB0 += v2 * w00 + v3 * w10;
        pB1 += v2 * w01 + v3 * w11;
        pB2 += v2 * w02 + v3 * w12;
    }
    #pragma unroll
    for (int d = 1; d < 4; d <<= 1) {
        pA0 += __shfl_xor_sync(0xffffffffu, pA0, d);
        pA1 += __shfl_xor_sync(0xffffffffu, pA1, d);
        pA2 += __shfl_xor_sync(0xffffffffu, pA2, d);
        pB0 += __shfl_xor_sync(0xffffffffu, pB0, d);
        pB1 += __shfl_xor_sync(0xffffffffu, pB1, d);
        pB2 += __shfl_xor_sync(0xffffffffu, pB2, d);
    }
    if ((lane & 3) == 0) {
        int r1 = row0 + warp * 16 + gr;
        float c0 = bh2[0], c1 = bh2[1], c2 = bh2[2];
        if (r1 < M) {
            g_delta[r1 * 3 + 0] = tanhf(pA0 + c0);
            g_delta[r1 * 3 + 1] = tanhf(pA1 + c1);
            g_delta[r1 * 3 + 2] = tanhf(pA2 + c2);
        }
        if (r1 + 8 < M) {
            g_delta[(r1 + 8) * 3 + 0] = tanhf(pB0 + c0);
            g_delta[(r1 + 8) * 3 + 1] = tanhf(pB1 + c1);
            g_delta[(r1 + 8) * 3 + 2] = tanhf(pB2 + c2);
        }
    }
}

// ---------------- agg: pure segmented max-gather of y (raw max, -inf if empty) ----------------
__global__ void agg_kernel(int N) {
    int warp = (blockIdx.x * blockDim.x + threadIdx.x) >> 5;
    int lane = threadIdx.x & 31;
    if (warp >= N) return;
    int c = lane * 4;
    int p0 = g_off[warp], p1 = g_off[warp + 1];
    float4 acc = make_float4(-INFINITY, -INFINITY, -INFINITY, -INFINITY);
    int p = p0;
    for (; p + 4 <= p1; p += 4) {
        int s0 = g_esrc[p + 0];
        int s1 = g_esrc[p + 1];
        int s2 = g_esrc[p + 2];
        int s3 = g_esrc[p + 3];
        float4 v0 = *(const float4*)&g_y[(size_t)s0 * 128 + c];
        float4 v1 = *(const float4*)&g_y[(size_t)s1 * 128 + c];
        float4 v2 = *(const float4*)&g_y[(size_t)s2 * 128 + c];
        float4 v3 = *(const float4*)&g_y[(size_t)s3 * 128 + c];
        acc.x = fmaxf(fmaxf(fmaxf(acc.x, v0.x), fmaxf(v1.x, v2.x)), v3.x);
        acc.y = fmaxf(fmaxf(fmaxf(acc.y, v0.y), fmaxf(v1.y, v2.y)), v3.y);
        acc.z = fmaxf(fmaxf(fmaxf(acc.z, v0.z), fmaxf(v1.z, v2.z)), v3.z);
        acc.w = fmaxf(fmaxf(fmaxf(acc.w, v0.w), fmaxf(v1.w, v2.w)), v3.w);
    }
    for (; p < p1; ++p) {
        int s = g_esrc[p];
        float4 v = *(const float4*)&g_y[(size_t)s * 128 + c];
        acc.x = fmaxf(acc.x, v.x);
        acc.y = fmaxf(acc.y, v.y);
        acc.z = fmaxf(acc.z, v.z);
        acc.w = fmaxf(acc.w, v.w);
    }
    *(float4*)&g_mx[(size_t)warp * 128 + c] = acc;
}

// ---------------- out = lrelu(agg@Wg1+bg1)@Wg2 + bg2 + x ----------------
// A-staging computes agg = lrelu(mx + c_d) with c_d = (delta_d - pos_d)·Wf_rel; empty -> 0.
#define MMA_SMEM_O (32768 * 2 + 34816 * 2 + 512 + 512 + 1536)
__global__ __launch_bounds__(256, 1)
void out_mma_kernel(const float* __restrict__ b1, const float* __restrict__ b2,
                    const float* __restrict__ X, const float* __restrict__ pos,
                    const float* __restrict__ Wf, float* __restrict__ O, int M) {
    extern __shared__ char smx[];
    unsigned int* Bh = (unsigned int*)smx;
    unsigned int* Bl = (unsigned int*)(smx + 32768);
    char* Ah = smx + 65536;
    char* Al = smx + 65536 + 34816;
    float* sb1 = (float*)(smx + 65536 + 69632);
    float* sb2 = (float*)(smx + 65536 + 69632 + 512);
    float* sWf = (float*)(smx + 65536 + 69632 + 1024);
    int tid = threadIdx.x, lane = tid & 31, warp = tid >> 5;
    int row0 = blockIdx.x * 128;
    int gr  = lane >> 2;
    int cc2 = (lane & 3) * 2;

    stage_B(g_bfh[2], g_bfl[2], Bh, Bl, tid);
    if (tid < 128) sb1[tid] = b1[tid];
    else if (tid < 256) sb2[tid - 128] = b2[tid - 128];
    if (tid < 96) *(float4*)&sWf[tid * 4] = *(const float4*)&Wf[tid * 4];
    __syncthreads();

    // stage A = lrelu(mx + c_d), split hi/lo
    #pragma unroll
    for (int it = 0; it < 16; it++) {
        int idx = it * 256 + tid;
        int r  = idx >> 5;
        int c4 = (idx & 31) * 4;
        int row = row0 + r;
        float4 v = make_float4(0.f, 0.f, 0.f, 0.f);
        if (row < M) {
            float4 t = *(const float4*)&g_mx[(size_t)row * 128 + c4];
            float dx = g_delta[row * 3 + 0] - pos[row * 3 + 0];
            float dy = g_delta[row * 3 + 1] - pos[row * 3 + 1];
            float dz = g_delta[row * 3 + 2] - pos[row * 3 + 2];
            float c0 = dx * sWf[c4 + 0] + dy * sWf[128 + c4 + 0] + dz * sWf[256 + c4 + 0];
            float c1 = dx * sWf[c4 + 1] + dy * sWf[128 + c4 + 1] + dz * sWf[256 + c4 + 1];
            float c2 = dx * sWf[c4 + 2] + dy * sWf[128 + c4 + 2] + dz * sWf[256 + c4 + 2];
            float c3 = dx * sWf[c4 + 3] + dy * sWf[128 + c4 + 3] + dz * sWf[256 + c4 + 3];
            v.x = (t.x == -INFINITY) ? 0.f : lrelu(t.x + c0);
            v.y = (t.y == -INFINITY) ? 0.f : lrelu(t.y + c1);
            v.z = (t.z == -INFINITY) ? 0.f : lrelu(t.z + c2);
            v.w = (t.w == -INFINITY) ? 0.f : lrelu(t.w + c3);
        }
        unsigned int h01 = pack_bf2(v.x, v.y);
        unsigned int h23 = pack_bf2(v.z, v.w);
        float hf0 = __uint_as_float(h01 << 16);
        float hf1 = __uint_as_float(h01 & 0xFFFF0000u);
        float hf2 = __uint_as_float(h23 << 16);
        float hf3 = __uint_as_float(h23 & 0xFFFF0000u);
        unsigned int l01 = pack_bf2(v.x - hf0, v.y - hf1);
        unsigned int l23 = pack_bf2(v.z - hf2, v.w - hf3);
        *(uint2*)(Ah + r * APITCH + c4 * 2) = make_uint2(h01, h23);
        *(uint2*)(Al + r * APITCH + c4 * 2) = make_uint2(l01, l23);
    }
    __syncthreads();

    float acc[16][4];
    #pragma unroll
    for (int j = 0; j < 16; j++)
        #pragma unroll
        for (int q = 0; q < 4; q++) acc[j][q] = 0.f;

    mma_mainloop(Ah, Al, Bh, Bl, acc, lane, warp);
    __syncthreads();

    // t = lrelu(acc + bg1) back into A tiles; restage B = Wg2
    {
        int rlA = warp * 16 + gr;
        #pragma unroll
        for (int j = 0; j < 16; j++) {
            int col = j * 8 + cc2;
            float b0 = sb1[col], b1v = sb1[col + 1];
            float v0 = lrelu(acc[j][0] + b0);
            float v1 = lrelu(acc[j][1] + b1v);
            float v2 = lrelu(acc[j][2] + b0);
            float v3 = lrelu(acc[j][3] + b1v);
            unsigned int hA = pack_bf2(v0, v1);
            unsigned int hB = pack_bf2(v2, v3);
            float hf0 = __uint_as_float(hA << 16);
            float hf1 = __uint_as_float(hA & 0xFFFF0000u);
            float hf2 = __uint_as_float(hB << 16);
            float hf3 = __uint_as_float(hB & 0xFFFF0000u);
            unsigned int lA = pack_bf2(v0 - hf0, v1 - hf1);
            unsigned int lB = pack_bf2(v2 - hf2, v3 - hf3);
            *(unsigned int*)(Ah + rlA * APITCH + col * 2) = hA;
            *(unsigned int*)(Al + rlA * APITCH + col * 2) = lA;
            *(unsigned int*)(Ah + (rlA + 8) * APITCH + col * 2) = hB;
            *(unsigned int*)(Al + (rlA + 8) * APITCH + col * 2) = lB;
        }
    }
    stage_B(g_bfh[3], g_bfl[3], Bh, Bl, tid);
    __syncthreads();

    #pragma unroll
    for (int j = 0; j < 16; j++)
        #pragma unroll
        for (int q = 0; q < 4; q++) acc[j][q] = 0.f;

    mma_mainloop(Ah, Al, Bh, Bl, acc, lane, warp);

    int r1 = row0 + warp * 16 + gr;
    #pragma unroll
    for (int j = 0; j < 16; j++) {
        int col = j * 8 + cc2;
        float b0 = sb2[col], b1v = sb2[col + 1];
        if (r1 < M) {
            float2 rx = *(const float2*)&X[(size_t)r1 * 128 + col];
            *(float2*)&O[(size_t)r1 * 128 + col] =
                make_float2(acc[j][0] + b0 + rx.x, acc[j][1] + b1v + rx.y);
        }
        if (r1 + 8 < M) {
            float2 rx = *(const float2*)&X[(size_t)(r1 + 8) * 128 + col];
            *(float2*)&O[(size_t)(r1 + 8) * 128 + col] =
                make_float2(acc[j][2] + b0 + rx.x, acc[j][3] + b1v + rx.y);
        }
    }
}

// ---------------- launch ----------------
extern "C" void kernel_launch(void* const* d_in, const int* in_sizes, int n_in,
                              void* d_out, int out_size) {
    const float* x   = (const float*)d_in[0];
    const float* pos = (const float*)d_in[1];
    const void*  ei  = d_in[2];
    const float* Wh1 = (const float*)d_in[3];
    const float* bh1 = (const float*)d_in[4];
    const float* Wh2 = (const float*)d_in[5];
    const float* bh2 = (const float*)d_in[6];
    const float* Wf  = (const float*)d_in[7];
    const float* bf  = (const float*)d_in[8];
    const float* Wg1 = (const float*)d_in[9];
    const float* bg1 = (const float*)d_in[10];
    const float* Wg2 = (const float*)d_in[11];
    const float* bg2 = (const float*)d_in[12];
    float* out = (float*)d_out;

    int M = in_sizes[0] / CDIM;   // 50000
    int E = in_sizes[2] / 2;      // 800000

    cudaFuncSetAttribute(xf_mma_kernel,     cudaFuncAttributeMaxDynamicSharedMemorySize, MMA_SMEM_XF);
    cudaFuncSetAttribute(hdelta_mma_kernel, cudaFuncAttributeMaxDynamicSharedMemorySize, MMA_SMEM_H);
    cudaFuncSetAttribute(out_mma_kernel,    cudaFuncAttributeMaxDynamicSharedMemorySize, MMA_SMEM_O);

    float* yp;
    cudaGetSymbolAddress((void**)&yp, g_y);

    int gemm_blocks = (M + 127) / 128;
    int eblocks = (E + 255) / 256;
    int nblocks = (M + 255) / 256;
    int sblocks = (M + 1023) / 1024;
    int wblocks = (M + 7) / 8;

    static cudaStream_t s_side = nullptr;
    static cudaEvent_t  s_e0 = nullptr, s_e1 = nullptr;
    if (s_side == nullptr) {
        cudaStreamCreateWithFlags(&s_side, cudaStreamNonBlocking);
        cudaEventCreateWithFlags(&s_e0, cudaEventDisableTiming);
        cudaEventCreateWithFlags(&s_e1, cudaEventDisableTiming);
    }

    // main: weight prep
    prep_w_kernel<<<dim3(16, 4), 256>>>(Wh1, Wf + 3 * 128, Wg1, Wg2);
    cudaEventRecord(s_e0, 0);

    // side branch: CSR build (hidden under xf + hdelta)
    cudaStreamWaitEvent(s_side, s_e0, 0);
    detect_kernel<<<1, 32, 0, s_side>>>((const unsigned int*)ei, E);
    zero_cnt_kernel<<<nblocks, 256, 0, s_side>>>(M);
    convert_hist_kernel<<<eblocks, 256, 0, s_side>>>(ei, E);
    scanA_kernel<<<sblocks, 1024, 0, s_side>>>(M);
    scanB_kernel<<<1, 64, 0, s_side>>>(sblocks);
    scanC_kernel<<<sblocks, 1024, 0, s_side>>>(M);
    scatter_kernel<<<eblocks, 256, 0, s_side>>>(E);
    cudaEventRecord(s_e1, s_side);

    // main: y GEMM, then hdelta (fills CSR wait), then max-gather, then out
    xf_mma_kernel<<<gemm_blocks, 256, MMA_SMEM_XF>>>(x, bf, pos, Wf, yp, M);
    hdelta_mma_kernel<<<gemm_blocks, 256, MMA_SMEM_H>>>(x, bh1, Wh2, bh2, M);
    cudaStreamWaitEvent(0, s_e1, 0);
    agg_kernel<<<wblocks, 256>>>(M);
    out_mma_kernel<<<gemm_blocks, 256, MMA_SMEM_O>>>(bg1, bg2, x, pos, Wf, out, M);
}

// round 13
// speedup vs baseline: 1.1105x; 1.0681x over previous
#include <cuda_runtime.h>
#include <cuda_fp16.h>
#include <math.h>
#include <stdint.h>

#define NMAX 50000
#define EMAX 800000
#define CDIM 128

// ---------------- device scratch ----------------
__device__ int   g_is64;
__device__ unsigned int g_yh[(size_t)NMAX * 64];   // y as half2 (64 u32 per row)
__device__ float g_mx [(size_t)NMAX * CDIM];       // segmented max of y (fp32, -inf if empty)
__device__ float g_delta[(size_t)NMAX * 3];
__device__ int   g_src [EMAX];
__device__ int   g_dst [EMAX];
__device__ int   g_esrc[EMAX];
__device__ int   g_cnt [NMAX];
__device__ int   g_cur [NMAX];
__device__ int   g_off [NMAX + 1];
__device__ int   g_bsum[64];
__device__ int   g_bpre[64];
// weights pre-split bf16 hi/lo in mma fragment order: 0=Wh1 1=WfX 2=Wg1 3=Wg2
__device__ unsigned int g_bfh[4][8192];
__device__ unsigned int g_bfl[4][8192];

// ---------------- helpers ----------------
__device__ __forceinline__ float lrelu(float v) { return (v > 0.f) ? v : 0.01f * v; }
__device__ __forceinline__ unsigned int pack_bf2(float e0, float e1) {
    unsigned int r;
    asm("cvt.rn.bf16x2.f32 %0, %1, %2;" : "=r"(r) : "f"(e1), "f"(e0));
    return r;
}
__device__ __forceinline__ void mma_bf16(float acc[4],
                                         unsigned int a0, unsigned int a1, unsigned int a2, unsigned int a3,
                                         unsigned int b0, unsigned int b1) {
    asm("mma.sync.aligned.m16n8k16.row.col.f32.bf16.bf16.f32 "
        "{%0,%1,%2,%3}, {%4,%5,%6,%7}, {%8,%9}, {%0,%1,%2,%3};"
        : "+f"(acc[0]), "+f"(acc[1]), "+f"(acc[2]), "+f"(acc[3])
        : "r"(a0), "r"(a1), "r"(a2), "r"(a3), "r"(b0), "r"(b1));
}

// ---------------- dtype detection ----------------
__global__ void detect_kernel(const unsigned int* __restrict__ w, int E) {
    int nz = 0;
    int lim = 2 * E;
    for (int i = threadIdx.x; i < 256; i += 32) {
        int wi = 2 * i + 1;
        if (wi < lim) nz |= (w[wi] != 0u);
    }
    nz = __any_sync(0xffffffffu, nz);
    if (threadIdx.x == 0) g_is64 = nz ? 0 : 1;
}

__global__ void zero_cnt_kernel(int n) {
    int i = blockIdx.x * blockDim.x + threadIdx.x;
    if (i < n) { g_cnt[i] = 0; g_cur[i] = 0; }
}

__global__ void convert_hist_kernel(const void* __restrict__ ei, int E) {
    int i = blockIdx.x * blockDim.x + threadIdx.x;
    if (i >= E) return;
    int s, d;
    if (g_is64) {
        const long long* p = (const long long*)ei;
        s = (int)p[i];
        d = (int)p[E + i];
    } else {
        const int* p = (const int*)ei;
        s = p[i];
        d = p[E + i];
    }
    g_src[i] = s;
    g_dst[i] = d;
    atomicAdd(&g_cnt[d], 1);
}

// ---------------- hierarchical scan ----------------
__global__ void scanA_kernel(int n) {
    __shared__ int wsum[32];
    int tid = threadIdx.x, lane = tid & 31, wid = tid >> 5;
    int i = blockIdx.x * 1024 + tid;
    int v = (i < n) ? g_cnt[i] : 0;
    int x = v;
    #pragma unroll
    for (int d = 1; d < 32; d <<= 1) {
        int t = __shfl_up_sync(0xffffffffu, x, d);
        if (lane >= d) x += t;
    }
    if (lane == 31) wsum[wid] = x;
    __syncthreads();
    if (wid == 0) {
        int s = wsum[lane];
        #pragma unroll
        for (int d = 1; d < 32; d <<= 1) {
            int t = __shfl_up_sync(0xffffffffu, s, d);
            if (lane >= d) s += t;
        }
        wsum[lane] = s;
    }
    __syncthreads();
    if (wid > 0) x += wsum[wid - 1];
    if (i < n) g_off[i + 1] = x;
    if (tid == 1023) g_bsum[blockIdx.x] = x;
}

__global__ void scanB_kernel(int nb) {
    __shared__ int ws[2];
    int t = threadIdx.x, lane = t & 31, w = t >> 5;
    int v = (t < nb) ? g_bsum[t] : 0;
    int x = v;
    #pragma unroll
    for (int d = 1; d < 32; d <<= 1) {
        int u = __shfl_up_sync(0xffffffffu, x, d);
        if (lane >= d) x += u;
    }
    if (lane == 31) ws[w] = x;
    __syncthreads();
    if (w == 1) x += ws[0];
    if (t < nb) g_bpre[t] = x - v;
}

__global__ void scanC_kernel(int n) {
    int i = blockIdx.x * 1024 + threadIdx.x;
    int add = g_bpre[blockIdx.x];
    if (i < n) g_off[i + 1] += add;
    if (i == 0) g_off[0] = 0;
}

__global__ void scatter_kernel(int E) {
    int i = blockIdx.x * blockDim.x + threadIdx.x;
    if (i >= E) return;
    int d = g_dst[i];
    int p = g_off[d] + atomicAdd(&g_cur[d], 1);
    g_esrc[p] = g_src[i];
}

// ---------------- weight prep: split bf16 hi/lo into mma fragment order ----------------
__global__ void prep_w_kernel(const float* __restrict__ Wh1, const float* __restrict__ WfX,
                              const float* __restrict__ Wg1, const float* __restrict__ Wg2) {
    const float* W = (blockIdx.y == 0) ? Wh1 : (blockIdx.y == 1) ? WfX :
                     (blockIdx.y == 2) ? Wg1 : Wg2;
    int idx = blockIdx.x * 256 + threadIdx.x;
    if (idx >= 4096) return;
    int t  = idx & 31;
    int j  = (idx >> 5) & 15;
    int ks = idx >> 9;
    int n  = j * 8 + (t >> 2);
    int k1 = ks * 16 + 2 * (t & 3);
    float w00 = W[k1 * 128 + n],       w01 = W[(k1 + 1) * 128 + n];
    float w10 = W[(k1 + 8) * 128 + n], w11 = W[(k1 + 9) * 128 + n];
    unsigned int h0 = pack_bf2(w00, w01);
    unsigned int h1 = pack_bf2(w10, w11);
    float hf00 = __uint_as_float(h0 << 16);
    float hf01 = __uint_as_float(h0 & 0xFFFF0000u);
    float hf10 = __uint_as_float(h1 << 16);
    float hf11 = __uint_as_float(h1 & 0xFFFF0000u);
    unsigned int l0 = pack_bf2(w00 - hf00, w01 - hf01);
    unsigned int l1 = pack_bf2(w10 - hf10, w11 - hf11);
    g_bfh[blockIdx.y][idx * 2 + 0] = h0;
    g_bfh[blockIdx.y][idx * 2 + 1] = h1;
    g_bfl[blockIdx.y][idx * 2 + 0] = l0;
    g_bfl[blockIdx.y][idx * 2 + 1] = l1;
}

// ---------------- shared mma building blocks ----------------
#define APITCH 272

__device__ __forceinline__ void stage_A_split(const float* __restrict__ A, int row0, int M,
                                              char* Ah, char* Al, int tid) {
    #pragma unroll
    for (int it = 0; it < 16; it++) {
        int idx = it * 256 + tid;
        int r  = idx >> 5;
        int c4 = (idx & 31) * 4;
        float4 v = make_float4(0.f, 0.f, 0.f, 0.f);
        if (row0 + r < M) v = *(const float4*)&A[(size_t)(row0 + r) * 128 + c4];
        unsigned int h01 = pack_bf2(v.x, v.y);
        unsigned int h23 = pack_bf2(v.z, v.w);
        float hf0 = __uint_as_float(h01 << 16);
        float hf1 = __uint_as_float(h01 & 0xFFFF0000u);
        float hf2 = __uint_as_float(h23 << 16);
        float hf3 = __uint_as_float(h23 & 0xFFFF0000u);
        unsigned int l01 = pack_bf2(v.x - hf0, v.y - hf1);
        unsigned int l23 = pack_bf2(v.z - hf2, v.w - hf3);
        *(uint2*)(Ah + r * APITCH + c4 * 2) = make_uint2(h01, h23);
        *(uint2*)(Al + r * APITCH + c4 * 2) = make_uint2(l01, l23);
    }
}

__device__ __forceinline__ void stage_B(const unsigned int* __restrict__ fh,
                                        const unsigned int* __restrict__ fl,
                                        unsigned int* Bh, unsigned int* Bl, int tid) {
    #pragma unroll
    for (int i = 0; i < 8; i++) {
        int idx = i * 256 + tid;
        ((uint4*)Bh)[idx] = ((const uint4*)fh)[idx];
        ((uint4*)Bl)[idx] = ((const uint4*)fl)[idx];
    }
}

__device__ __forceinline__ void mma_mainloop(const char* Ah, const char* Al,
                                             const unsigned int* Bh, const unsigned int* Bl,
                                             float acc[16][4], int lane, int warp) {
    int gr  = lane >> 2;
    int cc2 = (lane & 3) * 2;
    int abase = (warp * 16 + gr) * APITCH + cc2 * 2;
    #pragma unroll
    for (int ks = 0; ks < 8; ks++) {
        int ao = abase + ks * 32;
        unsigned int ah0 = *(const unsigned int*)(Ah + ao);
        unsigned int ah1 = *(const unsigned int*)(Ah + ao + 8 * APITCH);
        unsigned int ah2 = *(const unsigned int*)(Ah + ao + 16);
        unsigned int ah3 = *(const unsigned int*)(Ah + ao + 8 * APITCH + 16);
        unsigned int al0 = *(const unsigned int*)(Al + ao);
        unsigned int al1 = *(const unsigned int*)(Al + ao + 8 * APITCH);
        unsigned int al2 = *(const unsigned int*)(Al + ao + 16);
        unsigned int al3 = *(const unsigned int*)(Al + ao + 8 * APITCH + 16);
        #pragma unroll
        for (int jb = 0; jb < 4; jb++) {
            unsigned int bh[4][2], bl[4][2];
            #pragma unroll
            for (int q = 0; q < 4; q++) {
                int slot = ((ks * 16 + jb * 4 + q) * 32 + lane) * 2;
                uint2 t1 = *(const uint2*)&Bh[slot];
                uint2 t2 = *(const uint2*)&Bl[slot];
                bh[q][0] = t1.x; bh[q][1] = t1.y;
                bl[q][0] = t2.x; bl[q][1] = t2.y;
            }
            #pragma unroll
            for (int q = 0; q < 4; q++)
                mma_bf16(acc[jb * 4 + q], ah0, ah1, ah2, ah3, bh[q][0], bh[q][1]);
            #pragma unroll
            for (int q = 0; q < 4; q++)
                mma_bf16(acc[jb * 4 + q], ah0, ah1, ah2, ah3, bl[q][0], bl[q][1]);
            #pragma unroll
            for (int q = 0; q < 4; q++)
                mma_bf16(acc[jb * 4 + q], al0, al1, al2, al3, bh[q][0], bh[q][1]);
        }
    }
}

// ---------------- y = x @ WfX + bf + pos·Wf_rel  (stored as half2) ----------------
#define MMA_SMEM_XF (32768 * 2 + 34816 * 2 + 512 + 1536)
__global__ __launch_bounds__(256, 1)
void xf_mma_kernel(const float* __restrict__ A, const float* __restrict__ bias,
                   const float* __restrict__ pos, const float* __restrict__ Wf,
                   unsigned int* __restrict__ O, int M) {
    extern __shared__ char smx[];
    unsigned int* Bh = (unsigned int*)smx;
    unsigned int* Bl = (unsigned int*)(smx + 32768);
    char* Ah = smx + 65536;
    char* Al = smx + 65536 + 34816;
    float* sbias = (float*)(smx + 65536 + 69632);
    float* sWf   = (float*)(smx + 65536 + 69632 + 512);
    int tid = threadIdx.x, lane = tid & 31, warp = tid >> 5;
    int row0 = blockIdx.x * 128;

    stage_B(g_bfh[1], g_bfl[1], Bh, Bl, tid);
    if (tid < 128) sbias[tid] = bias[tid];
    if (tid >= 128 && tid < 224) *(float4*)&sWf[(tid - 128) * 4] = *(const float4*)&Wf[(tid - 128) * 4];
    stage_A_split(A, row0, M, Ah, Al, tid);
    __syncthreads();

    float acc[16][4];
    #pragma unroll
    for (int j = 0; j < 16; j++)
        #pragma unroll
        for (int q = 0; q < 4; q++) acc[j][q] = 0.f;

    mma_mainloop(Ah, Al, Bh, Bl, acc, lane, warp);

    int gr  = lane >> 2;
    int cc2 = (lane & 3) * 2;
    int r1 = row0 + warp * 16 + gr;
    float pAx = 0.f, pAy = 0.f, pAz = 0.f, pBx = 0.f, pBy = 0.f, pBz = 0.f;
    if (r1 < M)     { pAx = pos[r1 * 3]; pAy = pos[r1 * 3 + 1]; pAz = pos[r1 * 3 + 2]; }
    if (r1 + 8 < M) { pBx = pos[(r1 + 8) * 3]; pBy = pos[(r1 + 8) * 3 + 1]; pBz = pos[(r1 + 8) * 3 + 2]; }
    #pragma unroll
    for (int j = 0; j < 16; j++) {
        int col = j * 8 + cc2;
        float b0 = sbias[col], b1 = sbias[col + 1];
        float w00 = sWf[col], w10 = sWf[128 + col], w20 = sWf[256 + col];
        float w01 = sWf[col + 1], w11 = sWf[128 + col + 1], w21 = sWf[256 + col + 1];
        if (r1 < M) {
            float y0 = acc[j][0] + b0 + pAx * w00 + pAy * w10 + pAz * w20;
            float y1 = acc[j][1] + b1 + pAx * w01 + pAy * w11 + pAz * w21;
            __half2 h = __floats2half2_rn(y0, y1);
            O[(size_t)r1 * 64 + (col >> 1)] = *(unsigned int*)&h;
        }
        if (r1 + 8 < M) {
            float y2 = acc[j][2] + b0 + pBx * w00 + pBy * w10 + pBz * w20;
            float y3 = acc[j][3] + b1 + pBx * w01 + pBy * w11 + pBz * w21;
            __half2 h = __floats2half2_rn(y2, y3);
            O[(size_t)(r1 + 8) * 64 + (col >> 1)] = *(unsigned int*)&h;
        }
    }
}

// ---------------- delta = tanh(lrelu(x@Wh1+bh1) @ Wh2 + bh2) ----------------
#define MMA_SMEM_H (32768 * 2 + 34816 * 2 + 512 + 1536)
__global__ __launch_bounds__(256, 1)
void hdelta_mma_kernel(const float* __restrict__ A, const float* __restrict__ bias,
                       const float* __restrict__ Wh2, const float* __restrict__ bh2, int M) {
    extern __shared__ char smx[];
    unsigned int* Bh = (unsigned int*)smx;
    unsigned int* Bl = (unsigned int*)(smx + 32768);
    char* Ah = smx + 65536;
    char* Al = smx + 65536 + 34816;
    float* sbias = (float*)(smx + 65536 + 69632);
    float* sW2   = (float*)(smx + 65536 + 69632 + 512);
    int tid = threadIdx.x, lane = tid & 31, warp = tid >> 5;
    int row0 = blockIdx.x * 128;

    stage_B(g_bfh[0], g_bfl[0], Bh, Bl, tid);
    if (tid < 128) sbias[tid] = bias[tid];
    if (tid >= 128 && tid < 224) *(float4*)&sW2[(tid - 128) * 4] = *(const float4*)&Wh2[(tid - 128) * 4];
    stage_A_split(A, row0, M, Ah, Al, tid);
    __syncthreads();

    float acc[16][4];
    #pragma unroll
    for (int j = 0; j < 16; j++)
        #pragma unroll
        for (int q = 0; q < 4; q++) acc[j][q] = 0.f;

    mma_mainloop(Ah, Al, Bh, Bl, acc, lane, warp);

    int gr  = lane >> 2;
    int cc2 = (lane & 3) * 2;
    float pA0 = 0.f, pA1 = 0.f, pA2 = 0.f;
    float pB0 = 0.f, pB1 = 0.f, pB2 = 0.f;
    #pragma unroll
    for (int j = 0; j < 16; j++) {
        int col = j * 8 + cc2;
        float b0 = sbias[col], b1 = sbias[col + 1];
        float v0 = lrelu(acc[j][0] + b0);
        float v1 = lrelu(acc[j][1] + b1);
        float v2 = lrelu(acc[j][2] + b0);
        float v3 = lrelu(acc[j][3] + b1);
        float w00 = sW2[col * 3 + 0], w01 = sW2[col * 3 + 1], w02 = sW2[col * 3 + 2];
        float w10 = sW2[(col + 1) * 3 + 0], w11 = sW2[(col + 1) * 3 + 1], w12 = sW2[(col + 1) * 3 + 2];
        pA0 += v0 * w00 + v1 * w10;
        pA1 += v0 * w01 + v1 * w11;
        pA2 += v0 * w02 + v1 * w12;
        pB0 += v2 * w00 + v3 * w10;
        pB1 += v2 * w01 + v3 * w11;
        pB2 += v2 * w02 + v3 * w12;
    }
    #pragma unroll
    for (int d = 1; d < 4; d <<= 1) {
        pA0 += __shfl_xor_sync(0xffffffffu, pA0, d);
        pA1 += __shfl_xor_sync(0xffffffffu, pA1, d);
        pA2 += __shfl_xor_sync(0xffffffffu, pA2, d);
        pB0 += __shfl_xor_sync(0xffffffffu, pB0, d);
        pB1 += __shfl_xor_sync(0xffffffffu, pB1, d);
        pB2 += __shfl_xor_sync(0xffffffffu, pB2, d);
    }
    if ((lane & 3) == 0) {
        int r1 = row0 + warp * 16 + gr;
        float c0 = bh2[0], c1 = bh2[1], c2 = bh2[2];
        if (r1 < M) {
            g_delta[r1 * 3 + 0] = tanhf(pA0 + c0);
            g_delta[r1 * 3 + 1] = tanhf(pA1 + c1);
            g_delta[r1 * 3 + 2] = tanhf(pA2 + c2);
        }
        if (r1 + 8 < M) {
            g_delta[(r1 + 8) * 3 + 0] = tanhf(pB0 + c0);
            g_delta[(r1 + 8) * 3 + 1] = tanhf(pB1 + c1);
            g_delta[(r1 + 8) * 3 + 2] = tanhf(pB2 + c2);
        }
    }
}

// ---------------- agg: segmented max-gather of half2 y ----------------
__global__ void agg_kernel(int N) {
    int warp = (blockIdx.x * blockDim.x + threadIdx.x) >> 5;
    int lane = threadIdx.x & 31;
    if (warp >= N) return;
    int cw = lane * 2;            // u32 index within row (covers cols 4*lane..4*lane+3)
    int p0 = g_off[warp], p1 = g_off[warp + 1];
    float4 acc = make_float4(-INFINITY, -INFINITY, -INFINITY, -INFINITY);
    int p = p0;
    for (; p + 4 <= p1; p += 4) {
        int s0 = g_esrc[p + 0];
        int s1 = g_esrc[p + 1];
        int s2 = g_esrc[p + 2];
        int s3 = g_esrc[p + 3];
        uint2 u0 = *(const uint2*)&g_yh[(size_t)s0 * 64 + cw];
        uint2 u1 = *(const uint2*)&g_yh[(size_t)s1 * 64 + cw];
        uint2 u2 = *(const uint2*)&g_yh[(size_t)s2 * 64 + cw];
        uint2 u3 = *(const uint2*)&g_yh[(size_t)s3 * 64 + cw];
        float2 a0 = __half22float2(*(__half2*)&u0.x), b0 = __half22float2(*(__half2*)&u0.y);
        float2 a1 = __half22float2(*(__half2*)&u1.x), b1 = __half22float2(*(__half2*)&u1.y);
        float2 a2 = __half22float2(*(__half2*)&u2.x), b2 = __half22float2(*(__half2*)&u2.y);
        float2 a3 = __half22float2(*(__half2*)&u3.x), b3 = __half22float2(*(__half2*)&u3.y);
        acc.x = fmaxf(fmaxf(fmaxf(acc.x, a0.x), fmaxf(a1.x, a2.x)), a3.x);
        acc.y = fmaxf(fmaxf(fmaxf(acc.y, a0.y), fmaxf(a1.y, a2.y)), a3.y);
        acc.z = fmaxf(fmaxf(fmaxf(acc.z, b0.x), fmaxf(b1.x, b2.x)), b3.x);
        acc.w = fmaxf(fmaxf(fmaxf(acc.w, b0.y), fmaxf(b1.y, b2.y)), b3.y);
    }
    for (; p < p1; ++p) {
        int s = g_esrc[p];
        uint2 u = *(const uint2*)&g_yh[(size_t)s * 64 + cw];
        float2 a = __half22float2(*(__half2*)&u.x);
        float2 b = __half22float2(*(__half2*)&u.y);
        acc.x = fmaxf(acc.x, a.x);
        acc.y = fmaxf(acc.y, a.y);
        acc.z = fmaxf(acc.z, b.x);
        acc.w = fmaxf(acc.w, b.y);
    }
    *(float4*)&g_mx[(size_t)warp * 128 + lane * 4] = acc;
}

// ---------------- out = lrelu(agg@Wg1+bg1)@Wg2 + bg2 + x ----------------
#define MMA_SMEM_O (32768 * 2 + 34816 * 2 + 512 + 512 + 1536)
__global__ __launch_bounds__(256, 1)
void out_mma_kernel(const float* __restrict__ b1, const float* __restrict__ b2,
                    const float* __restrict__ X, const float* __restrict__ pos,
                    const float* __restrict__ Wf, float* __restrict__ O, int M) {
    extern __shared__ char smx[];
    unsigned int* Bh = (unsigned int*)smx;
    unsigned int* Bl = (unsigned int*)(smx + 32768);
    char* Ah = smx + 65536;
    char* Al = smx + 65536 + 34816;
    float* sb1 = (float*)(smx + 65536 + 69632);
    float* sb2 = (float*)(smx + 65536 + 69632 + 512);
    float* sWf = (float*)(smx + 65536 + 69632 + 1024);
    int tid = threadIdx.x, lane = tid & 31, warp = tid >> 5;
    int row0 = blockIdx.x * 128;
    int gr  = lane >> 2;
    int cc2 = (lane & 3) * 2;

    stage_B(g_bfh[2], g_bfl[2], Bh, Bl, tid);
    if (tid < 128) sb1[tid] = b1[tid];
    else if (tid < 256) sb2[tid - 128] = b2[tid - 128];
    if (tid < 96) *(float4*)&sWf[tid * 4] = *(const float4*)&Wf[tid * 4];
    __syncthreads();

    // stage A = lrelu(mx + c_d), split hi/lo
    #pragma unroll
    for (int it = 0; it < 16; it++) {
        int idx = it * 256 + tid;
        int r  = idx >> 5;
        int c4 = (idx & 31) * 4;
        int row = row0 + r;
        float4 v = make_float4(0.f, 0.f, 0.f, 0.f);
        if (row < M) {
            float4 t = *(const float4*)&g_mx[(size_t)row * 128 + c4];
            float dx = g_delta[row * 3 + 0] - pos[row * 3 + 0];
            float dy = g_delta[row * 3 + 1] - pos[row * 3 + 1];
            float dz = g_delta[row * 3 + 2] - pos[row * 3 + 2];
            float c0 = dx * sWf[c4 + 0] + dy * sWf[128 + c4 + 0] + dz * sWf[256 + c4 + 0];
            float c1 = dx * sWf[c4 + 1] + dy * sWf[128 + c4 + 1] + dz * sWf[256 + c4 + 1];
            float c2 = dx * sWf[c4 + 2] + dy * sWf[128 + c4 + 2] + dz * sWf[256 + c4 + 2];
            float c3 = dx * sWf[c4 + 3] + dy * sWf[128 + c4 + 3] + dz * sWf[256 + c4 + 3];
            v.x = (t.x == -INFINITY) ? 0.f : lrelu(t.x + c0);
            v.y = (t.y == -INFINITY) ? 0.f : lrelu(t.y + c1);
            v.z = (t.z == -INFINITY) ? 0.f : lrelu(t.z + c2);
            v.w = (t.w == -INFINITY) ? 0.f : lrelu(t.w + c3);
        }
        unsigned int h01 = pack_bf2(v.x, v.y);
        unsigned int h23 = pack_bf2(v.z, v.w);
        float hf0 = __uint_as_float(h01 << 16);
        float hf1 = __uint_as_float(h01 & 0xFFFF0000u);
        float hf2 = __uint_as_float(h23 << 16);
        float hf3 = __uint_as_float(h23 & 0xFFFF0000u);
        unsigned int l01 = pack_bf2(v.x - hf0, v.y - hf1);
        unsigned int l23 = pack_bf2(v.z - hf2, v.w - hf3);
        *(uint2*)(Ah + r * APITCH + c4 * 2) = make_uint2(h01, h23);
        *(uint2*)(Al + r * APITCH + c4 * 2) = make_uint2(l01, l23);
    }
    __syncthreads();

    float acc[16][4];
    #pragma unroll
    for (int j = 0; j < 16; j++)
        #pragma unroll
        for (int q = 0; q < 4; q++) acc[j][q] = 0.f;

    mma_mainloop(Ah, Al, Bh, Bl, acc, lane, warp);
    __syncthreads();

    // t = lrelu(acc + bg1) back into A tiles; restage B = Wg2
    {
        int rlA = warp * 16 + gr;
        #pragma unroll
        for (int j = 0; j < 16; j++) {
            int col = j * 8 + cc2;
            float b0 = sb1[col], b1v = sb1[col + 1];
            float v0 = lrelu(acc[j][0] + b0);
            float v1 = lrelu(acc[j][1] + b1v);
            float v2 = lrelu(acc[j][2] + b0);
            float v3 = lrelu(acc[j][3] + b1v);
            unsigned int hA = pack_bf2(v0, v1);
            unsigned int hB = pack_bf2(v2, v3);
            float hf0 = __uint_as_float(hA << 16);
            float hf1 = __uint_as_float(hA & 0xFFFF0000u);
            float hf2 = __uint_as_float(hB << 16);
            float hf3 = __uint_as_float(hB & 0xFFFF0000u);
            unsigned int lA = pack_bf2(v0 - hf0, v1 - hf1);
            unsigned int lB = pack_bf2(v2 - hf2, v3 - hf3);
            *(unsigned int*)(Ah + rlA * APITCH + col * 2) = hA;
            *(unsigned int*)(Al + rlA * APITCH + col * 2) = lA;
            *(unsigned int*)(Ah + (rlA + 8) * APITCH + col * 2) = hB;
            *(unsigned int*)(Al + (rlA + 8) * APITCH + col * 2) = lB;
        }
    }
    stage_B(g_bfh[3], g_bfl[3], Bh, Bl, tid);
    __syncthreads();

    #pragma unroll
    for (int j = 0; j < 16; j++)
        #pragma unroll
        for (int q = 0; q < 4; q++) acc[j][q] = 0.f;

    mma_mainloop(Ah, Al, Bh, Bl, acc, lane, warp);

    int r1 = row0 + warp * 16 + gr;
    #pragma unroll
    for (int j = 0; j < 16; j++) {
        int col = j * 8 + cc2;
        float b0 = sb2[col], b1v = sb2[col + 1];
        if (r1 < M) {
            float2 rx = *(const float2*)&X[(size_t)r1 * 128 + col];
            *(float2*)&O[(size_t)r1 * 128 + col] =
                make_float2(acc[j][0] + b0 + rx.x, acc[j][1] + b1v + rx.y);
        }
        if (r1 + 8 < M) {
            float2 rx = *(const float2*)&X[(size_t)(r1 + 8) * 128 + col];
            *(float2*)&O[(size_t)(r1 + 8) * 128 + col] =
                make_float2(acc[j][2] + b0 + rx.x, acc[j][3] + b1v + rx.y);
        }
    }
}

// ---------------- launch ----------------
extern "C" void kernel_launch(void* const* d_in, const int* in_sizes, int n_in,
                              void* d_out, int out_size) {
    const float* x   = (const float*)d_in[0];
    const float* pos = (const float*)d_in[1];
    const void*  ei  = d_in[2];
    const float* Wh1 = (const float*)d_in[3];
    const float* bh1 = (const float*)d_in[4];
    const float* Wh2 = (const float*)d_in[5];
    const float* bh2 = (const float*)d_in[6];
    const float* Wf  = (const float*)d_in[7];
    const float* bf  = (const float*)d_in[8];
    const float* Wg1 = (const float*)d_in[9];
    const float* bg1 = (const float*)d_in[10];
    const float* Wg2 = (const float*)d_in[11];
    const float* bg2 = (const float*)d_in[12];
    float* out = (float*)d_out;

    int M = in_sizes[0] / CDIM;   // 50000
    int E = in_sizes[2] / 2;      // 800000

    cudaFuncSetAttribute(xf_mma_kernel,     cudaFuncAttributeMaxDynamicSharedMemorySize, MMA_SMEM_XF);
    cudaFuncSetAttribute(hdelta_mma_kernel, cudaFuncAttributeMaxDynamicSharedMemorySize, MMA_SMEM_H);
    cudaFuncSetAttribute(out_mma_kernel,    cudaFuncAttributeMaxDynamicSharedMemorySize, MMA_SMEM_O);

    unsigned int* yhp;
    cudaGetSymbolAddress((void**)&yhp, g_yh);

    int gemm_blocks = (M + 127) / 128;
    int eblocks = (E + 255) / 256;
    int nblocks = (M + 255) / 256;
    int sblocks = (M + 1023) / 1024;
    int wblocks = (M + 7) / 8;

    static cudaStream_t s_side = nullptr;
    static cudaEvent_t  s_e0 = nullptr, s_e1 = nullptr;
    if (s_side == nullptr) {
        cudaStreamCreateWithFlags(&s_side, cudaStreamNonBlocking);
        cudaEventCreateWithFlags(&s_e0, cudaEventDisableTiming);
        cudaEventCreateWithFlags(&s_e1, cudaEventDisableTiming);
    }

    // main: weight prep
    prep_w_kernel<<<dim3(16, 4), 256>>>(Wh1, Wf + 3 * 128, Wg1, Wg2);
    cudaEventRecord(s_e0, 0);

    // side branch: CSR build (hidden under xf + hdelta)
    cudaStreamWaitEvent(s_side, s_e0, 0);
    detect_kernel<<<1, 32, 0, s_side>>>((const unsigned int*)ei, E);
    zero_cnt_kernel<<<nblocks, 256, 0, s_side>>>(M);
    convert_hist_kernel<<<eblocks, 256, 0, s_side>>>(ei, E);
    scanA_kernel<<<sblocks, 1024, 0, s_side>>>(M);
    scanB_kernel<<<1, 64, 0, s_side>>>(sblocks);
    scanC_kernel<<<sblocks, 1024, 0, s_side>>>(M);
    scatter_kernel<<<eblocks, 256, 0, s_side>>>(E);
    cudaEventRecord(s_e1, s_side);

    // main: y GEMM, then hdelta (fills CSR wait), then max-gather, then out
    xf_mma_kernel<<<gemm_blocks, 256, MMA_SMEM_XF>>>(x, bf, pos, Wf, yhp, M);
    hdelta_mma_kernel<<<gemm_blocks, 256, MMA_SMEM_H>>>(x, bh1, Wh2, bh2, M);
    cudaStreamWaitEvent(0, s_e1, 0);
    agg_kernel<<<wblocks, 256>>>(M);
    out_mma_kernel<<<gemm_blocks, 256, MMA_SMEM_O>>>(bg1, bg2, x, pos, Wf, out, M);
}

// round 14
// speedup vs baseline: 1.1486x; 1.0343x over previous
#include <cuda_runtime.h>
#include <cuda_fp16.h>
#include <math.h>
#include <stdint.h>

#define NMAX 50000
#define EMAX 800000
#define CDIM 128

// ---------------- device scratch ----------------
__device__ int   g_is64;
__device__ unsigned int g_yh[(size_t)NMAX * 64];   // y as half2 (64 u32 per row)
__device__ float g_mx [(size_t)NMAX * CDIM];       // segmented max of y (fp32, -inf if empty)
__device__ float g_delta[(size_t)NMAX * 3];
__device__ int   g_src [EMAX];
__device__ int   g_dst [EMAX];
__device__ int   g_esrc[EMAX];
__device__ int   g_cnt [NMAX];
__device__ int   g_cur [NMAX];
__device__ int   g_off [NMAX + 1];
__device__ int   g_bsum[64];
__device__ int   g_bpre[64];
// weights pre-split bf16 hi/lo in mma fragment order: 0=Wh1 1=WfX 2=Wg1 3=Wg2
__device__ unsigned int g_bfh[4][8192];
__device__ unsigned int g_bfl[4][8192];

// ---------------- helpers ----------------
__device__ __forceinline__ float lrelu(float v) { return (v > 0.f) ? v : 0.01f * v; }
__device__ __forceinline__ unsigned int pack_bf2(float e0, float e1) {
    unsigned int r;
    asm("cvt.rn.bf16x2.f32 %0, %1, %2;" : "=r"(r) : "f"(e1), "f"(e0));
    return r;
}
__device__ __forceinline__ void mma_bf16(float acc[4],
                                         unsigned int a0, unsigned int a1, unsigned int a2, unsigned int a3,
                                         unsigned int b0, unsigned int b1) {
    asm("mma.sync.aligned.m16n8k16.row.col.f32.bf16.bf16.f32 "
        "{%0,%1,%2,%3}, {%4,%5,%6,%7}, {%8,%9}, {%0,%1,%2,%3};"
        : "+f"(acc[0]), "+f"(acc[1]), "+f"(acc[2]), "+f"(acc[3])
        : "r"(a0), "r"(a1), "r"(a2), "r"(a3), "r"(b0), "r"(b1));
}

// ---------------- dtype detection ----------------
__global__ void detect_kernel(const unsigned int* __restrict__ w, int E) {
    int nz = 0;
    int lim = 2 * E;
    for (int i = threadIdx.x; i < 256; i += 32) {
        int wi = 2 * i + 1;
        if (wi < lim) nz |= (w[wi] != 0u);
    }
    nz = __any_sync(0xffffffffu, nz);
    if (threadIdx.x == 0) g_is64 = nz ? 0 : 1;
}

__global__ void zero_cnt_kernel(int n) {
    int i = blockIdx.x * blockDim.x + threadIdx.x;
    if (i < n) { g_cnt[i] = 0; g_cur[i] = 0; }
}

__global__ void convert_hist_kernel(const void* __restrict__ ei, int E) {
    int i = blockIdx.x * blockDim.x + threadIdx.x;
    if (i >= E) return;
    int s, d;
    if (g_is64) {
        const long long* p = (const long long*)ei;
        s = (int)p[i];
        d = (int)p[E + i];
    } else {
        const int* p = (const int*)ei;
        s = p[i];
        d = p[E + i];
    }
    g_src[i] = s;
    g_dst[i] = d;
    atomicAdd(&g_cnt[d], 1);
}

// ---------------- hierarchical scan ----------------
__global__ void scanA_kernel(int n) {
    __shared__ int wsum[32];
    int tid = threadIdx.x, lane = tid & 31, wid = tid >> 5;
    int i = blockIdx.x * 1024 + tid;
    int v = (i < n) ? g_cnt[i] : 0;
    int x = v;
    #pragma unroll
    for (int d = 1; d < 32; d <<= 1) {
        int t = __shfl_up_sync(0xffffffffu, x, d);
        if (lane >= d) x += t;
    }
    if (lane == 31) wsum[wid] = x;
    __syncthreads();
    if (wid == 0) {
        int s = wsum[lane];
        #pragma unroll
        for (int d = 1; d < 32; d <<= 1) {
            int t = __shfl_up_sync(0xffffffffu, s, d);
            if (lane >= d) s += t;
        }
        wsum[lane] = s;
    }
    __syncthreads();
    if (wid > 0) x += wsum[wid - 1];
    if (i < n) g_off[i + 1] = x;
    if (tid == 1023) g_bsum[blockIdx.x] = x;
}

__global__ void scanB_kernel(int nb) {
    __shared__ int ws[2];
    int t = threadIdx.x, lane = t & 31, w = t >> 5;
    int v = (t < nb) ? g_bsum[t] : 0;
    int x = v;
    #pragma unroll
    for (int d = 1; d < 32; d <<= 1) {
        int u = __shfl_up_sync(0xffffffffu, x, d);
        if (lane >= d) x += u;
    }
    if (lane == 31) ws[w] = x;
    __syncthreads();
    if (w == 1) x += ws[0];
    if (t < nb) g_bpre[t] = x - v;
}

__global__ void scanC_kernel(int n) {
    int i = blockIdx.x * 1024 + threadIdx.x;
    int add = g_bpre[blockIdx.x];
    if (i < n) g_off[i + 1] += add;
    if (i == 0) g_off[0] = 0;
}

__global__ void scatter_kernel(int E) {
    int i = blockIdx.x * blockDim.x + threadIdx.x;
    if (i >= E) return;
    int d = g_dst[i];
    int p = g_off[d] + atomicAdd(&g_cur[d], 1);
    g_esrc[p] = g_src[i];
}

// ---------------- weight prep: split bf16 hi/lo into mma fragment order ----------------
__global__ void prep_w_kernel(const float* __restrict__ Wh1, const float* __restrict__ WfX,
                              const float* __restrict__ Wg1, const float* __restrict__ Wg2) {
    const float* W = (blockIdx.y == 0) ? Wh1 : (blockIdx.y == 1) ? WfX :
                     (blockIdx.y == 2) ? Wg1 : Wg2;
    int idx = blockIdx.x * 256 + threadIdx.x;
    if (idx >= 4096) return;
    int t  = idx & 31;
    int j  = (idx >> 5) & 15;
    int ks = idx >> 9;
    int n  = j * 8 + (t >> 2);
    int k1 = ks * 16 + 2 * (t & 3);
    float w00 = W[k1 * 128 + n],       w01 = W[(k1 + 1) * 128 + n];
    float w10 = W[(k1 + 8) * 128 + n], w11 = W[(k1 + 9) * 128 + n];
    unsigned int h0 = pack_bf2(w00, w01);
    unsigned int h1 = pack_bf2(w10, w11);
    float hf00 = __uint_as_float(h0 << 16);
    float hf01 = __uint_as_float(h0 & 0xFFFF0000u);
    float hf10 = __uint_as_float(h1 << 16);
    float hf11 = __uint_as_float(h1 & 0xFFFF0000u);
    unsigned int l0 = pack_bf2(w00 - hf00, w01 - hf01);
    unsigned int l1 = pack_bf2(w10 - hf10, w11 - hf11);
    g_bfh[blockIdx.y][idx * 2 + 0] = h0;
    g_bfh[blockIdx.y][idx * 2 + 1] = h1;
    g_bfl[blockIdx.y][idx * 2 + 0] = l0;
    g_bfl[blockIdx.y][idx * 2 + 1] = l1;
}

// ---------------- shared mma building blocks ----------------
#define APITCH 272

__device__ __forceinline__ void stage_B(const unsigned int* __restrict__ fh,
                                        const unsigned int* __restrict__ fl,
                                        unsigned int* Bh, unsigned int* Bl, int tid) {
    #pragma unroll
    for (int i = 0; i < 8; i++) {
        int idx = i * 256 + tid;
        ((uint4*)Bh)[idx] = ((const uint4*)fh)[idx];
        ((uint4*)Bl)[idx] = ((const uint4*)fl)[idx];
    }
}

// split fp32 pair into bf16x2 hi + lo
__device__ __forceinline__ void split2(float2 v, unsigned int& h, unsigned int& l) {
    h = pack_bf2(v.x, v.y);
    float hf0 = __uint_as_float(h << 16);
    float hf1 = __uint_as_float(h & 0xFFFF0000u);
    l = pack_bf2(v.x - hf0, v.y - hf1);
}

// register-A mainloop: A fragments loaded directly from gmem (fp32 row-major [*,128])
__device__ __forceinline__ void mma_mainloop_regA(
    const float* __restrict__ rowA, const float* __restrict__ rowB, bool okA, bool okB,
    const unsigned int* Bh, const unsigned int* Bl,
    float acc[16][4], int lane)
{
    int cc2 = (lane & 3) * 2;
    #pragma unroll
    for (int ks = 0; ks < 8; ks++) {
        int k0 = ks * 16 + cc2;
        float2 vA0 = make_float2(0.f, 0.f), vA1 = vA0, vB0 = vA0, vB1 = vA0;
        if (okA) { vA0 = *(const float2*)&rowA[k0]; vA1 = *(const float2*)&rowA[k0 + 8]; }
        if (okB) { vB0 = *(const float2*)&rowB[k0]; vB1 = *(const float2*)&rowB[k0 + 8]; }
        unsigned int ah0, ah1, ah2, ah3, al0, al1, al2, al3;
        split2(vA0, ah0, al0);
        split2(vB0, ah1, al1);
        split2(vA1, ah2, al2);
        split2(vB1, ah3, al3);
        #pragma unroll
        for (int jb = 0; jb < 4; jb++) {
            unsigned int bh[4][2], bl[4][2];
            #pragma unroll
            for (int q = 0; q < 4; q++) {
                int slot = ((ks * 16 + jb * 4 + q) * 32 + lane) * 2;
                uint2 t1 = *(const uint2*)&Bh[slot];
                uint2 t2 = *(const uint2*)&Bl[slot];
                bh[q][0] = t1.x; bh[q][1] = t1.y;
                bl[q][0] = t2.x; bl[q][1] = t2.y;
            }
            #pragma unroll
            for (int q = 0; q < 4; q++)
                mma_bf16(acc[jb * 4 + q], ah0, ah1, ah2, ah3, bh[q][0], bh[q][1]);
            #pragma unroll
            for (int q = 0; q < 4; q++)
                mma_bf16(acc[jb * 4 + q], ah0, ah1, ah2, ah3, bl[q][0], bl[q][1]);
            #pragma unroll
            for (int q = 0; q < 4; q++)
                mma_bf16(acc[jb * 4 + q], al0, al1, al2, al3, bh[q][0], bh[q][1]);
        }
    }
}

// smem-A mainloop (used by out_mma, which must round-trip t through smem)
__device__ __forceinline__ void mma_mainloop(const char* Ah, const char* Al,
                                             const unsigned int* Bh, const unsigned int* Bl,
                                             float acc[16][4], int lane, int warp) {
    int gr  = lane >> 2;
    int cc2 = (lane & 3) * 2;
    int abase = (warp * 16 + gr) * APITCH + cc2 * 2;
    #pragma unroll
    for (int ks = 0; ks < 8; ks++) {
        int ao = abase + ks * 32;
        unsigned int ah0 = *(const unsigned int*)(Ah + ao);
        unsigned int ah1 = *(const unsigned int*)(Ah + ao + 8 * APITCH);
        unsigned int ah2 = *(const unsigned int*)(Ah + ao + 16);
        unsigned int ah3 = *(const unsigned int*)(Ah + ao + 8 * APITCH + 16);
        unsigned int al0 = *(const unsigned int*)(Al + ao);
        unsigned int al1 = *(const unsigned int*)(Al + ao + 8 * APITCH);
        unsigned int al2 = *(const unsigned int*)(Al + ao + 16);
        unsigned int al3 = *(const unsigned int*)(Al + ao + 8 * APITCH + 16);
        #pragma unroll
        for (int jb = 0; jb < 4; jb++) {
            unsigned int bh[4][2], bl[4][2];
            #pragma unroll
            for (int q = 0; q < 4; q++) {
                int slot = ((ks * 16 + jb * 4 + q) * 32 + lane) * 2;
                uint2 t1 = *(const uint2*)&Bh[slot];
                uint2 t2 = *(const uint2*)&Bl[slot];
                bh[q][0] = t1.x; bh[q][1] = t1.y;
                bl[q][0] = t2.x; bl[q][1] = t2.y;
            }
            #pragma unroll
            for (int q = 0; q < 4; q++)
                mma_bf16(acc[jb * 4 + q], ah0, ah1, ah2, ah3, bh[q][0], bh[q][1]);
            #pragma unroll
            for (int q = 0; q < 4; q++)
                mma_bf16(acc[jb * 4 + q], ah0, ah1, ah2, ah3, bl[q][0], bl[q][1]);
            #pragma unroll
            for (int q = 0; q < 4; q++)
                mma_bf16(acc[jb * 4 + q], al0, al1, al2, al3, bh[q][0], bh[q][1]);
        }
    }
}

// ---------------- y = x @ WfX + bf + pos·Wf_rel  (stored as half2); occ 2 ----------------
#define MMA_SMEM_XF (32768 * 2 + 512 + 1536)
__global__ __launch_bounds__(256, 2)
void xf_mma_kernel(const float* __restrict__ A, const float* __restrict__ bias,
                   const float* __restrict__ pos, const float* __restrict__ Wf,
                   unsigned int* __restrict__ O, int M) {
    extern __shared__ char smx[];
    unsigned int* Bh = (unsigned int*)smx;
    unsigned int* Bl = (unsigned int*)(smx + 32768);
    float* sbias = (float*)(smx + 65536);
    float* sWf   = (float*)(smx + 65536 + 512);
    int tid = threadIdx.x, lane = tid & 31, warp = tid >> 5;
    int row0 = blockIdx.x * 128;

    stage_B(g_bfh[1], g_bfl[1], Bh, Bl, tid);
    if (tid < 128) sbias[tid] = bias[tid];
    if (tid >= 128 && tid < 224) *(float4*)&sWf[(tid - 128) * 4] = *(const float4*)&Wf[(tid - 128) * 4];
    __syncthreads();

    int gr  = lane >> 2;
    int cc2 = (lane & 3) * 2;
    int r1 = row0 + warp * 16 + gr;
    bool okA = r1 < M, okB = (r1 + 8) < M;
    const float* rowA = A + (size_t)r1 * 128;
    const float* rowB = A + (size_t)(r1 + 8) * 128;

    float acc[16][4];
    #pragma unroll
    for (int j = 0; j < 16; j++)
        #pragma unroll
        for (int q = 0; q < 4; q++) acc[j][q] = 0.f;

    mma_mainloop_regA(rowA, rowB, okA, okB, Bh, Bl, acc, lane);

    float pAx = 0.f, pAy = 0.f, pAz = 0.f, pBx = 0.f, pBy = 0.f, pBz = 0.f;
    if (okA) { pAx = pos[r1 * 3]; pAy = pos[r1 * 3 + 1]; pAz = pos[r1 * 3 + 2]; }
    if (okB) { pBx = pos[(r1 + 8) * 3]; pBy = pos[(r1 + 8) * 3 + 1]; pBz = pos[(r1 + 8) * 3 + 2]; }
    #pragma unroll
    for (int j = 0; j < 16; j++) {
        int col = j * 8 + cc2;
        float b0 = sbias[col], b1 = sbias[col + 1];
        float w00 = sWf[col], w10 = sWf[128 + col], w20 = sWf[256 + col];
        float w01 = sWf[col + 1], w11 = sWf[128 + col + 1], w21 = sWf[256 + col + 1];
        if (okA) {
            float y0 = acc[j][0] + b0 + pAx * w00 + pAy * w10 + pAz * w20;
            float y1 = acc[j][1] + b1 + pAx * w01 + pAy * w11 + pAz * w21;
            __half2 h = __floats2half2_rn(y0, y1);
            O[(size_t)r1 * 64 + (col >> 1)] = *(unsigned int*)&h;
        }
        if (okB) {
            float y2 = acc[j][2] + b0 + pBx * w00 + pBy * w10 + pBz * w20;
            float y3 = acc[j][3] + b1 + pBx * w01 + pBy * w11 + pBz * w21;
            __half2 h = __floats2half2_rn(y2, y3);
            O[(size_t)(r1 + 8) * 64 + (col >> 1)] = *(unsigned int*)&h;
        }
    }
}

// ---------------- delta = tanh(lrelu(x@Wh1+bh1) @ Wh2 + bh2); occ 2 ----------------
#define MMA_SMEM_H (32768 * 2 + 512 + 1536)
__global__ __launch_bounds__(256, 2)
void hdelta_mma_kernel(const float* __restrict__ A, const float* __restrict__ bias,
                       const float* __restrict__ Wh2, const float* __restrict__ bh2, int M) {
    extern __shared__ char smx[];
    unsigned int* Bh = (unsigned int*)smx;
    unsigned int* Bl = (unsigned int*)(smx + 32768);
    float* sbias = (float*)(smx + 65536);
    float* sW2   = (float*)(smx + 65536 + 512);
    int tid = threadIdx.x, lane = tid & 31, warp = tid >> 5;
    int row0 = blockIdx.x * 128;

    stage_B(g_bfh[0], g_bfl[0], Bh, Bl, tid);
    if (tid < 128) sbias[tid] = bias[tid];
    if (tid >= 128 && tid < 224) *(float4*)&sW2[(tid - 128) * 4] = *(const float4*)&Wh2[(tid - 128) * 4];
    __syncthreads();

    int gr  = lane >> 2;
    int cc2 = (lane & 3) * 2;
    int r1 = row0 + warp * 16 + gr;
    bool okA = r1 < M, okB = (r1 + 8) < M;
    const float* rowA = A + (size_t)r1 * 128;
    const float* rowB = A + (size_t)(r1 + 8) * 128;

    float acc[16][4];
    #pragma unroll
    for (int j = 0; j < 16; j++)
        #pragma unroll
        for (int q = 0; q < 4; q++) acc[j][q] = 0.f;

    mma_mainloop_regA(rowA, rowB, okA, okB, Bh, Bl, acc, lane);

    float pA0 = 0.f, pA1 = 0.f, pA2 = 0.f;
    float pB0 = 0.f, pB1 = 0.f, pB2 = 0.f;
    #pragma unroll
    for (int j = 0; j < 16; j++) {
        int col = j * 8 + cc2;
        float b0 = sbias[col], b1 = sbias[col + 1];
        float v0 = lrelu(acc[j][0] + b0);
        float v1 = lrelu(acc[j][1] + b1);
        float v2 = lrelu(acc[j][2] + b0);
        float v3 = lrelu(acc[j][3] + b1);
        float w00 = sW2[col * 3 + 0], w01 = sW2[col * 3 + 1], w02 = sW2[col * 3 + 2];
        float w10 = sW2[(col + 1) * 3 + 0], w11 = sW2[(col + 1) * 3 + 1], w12 = sW2[(col + 1) * 3 + 2];
        pA0 += v0 * w00 + v1 * w10;
        pA1 += v0 * w01 + v1 * w11;
        pA2 += v0 * w02 + v1 * w12;
        pB0 += v2 * w00 + v3 * w10;
        pB1 += v2 * w01 + v3 * w11;
        pB2 += v2 * w02 + v3 * w12;
    }
    #pragma unroll
    for (int d = 1; d < 4; d <<= 1) {
        pA0 += __shfl_xor_sync(0xffffffffu, pA0, d);
        pA1 += __shfl_xor_sync(0xffffffffu, pA1, d);
        pA2 += __shfl_xor_sync(0xffffffffu, pA2, d);
        pB0 += __shfl_xor_sync(0xffffffffu, pB0, d);
        pB1 += __shfl_xor_sync(0xffffffffu, pB1, d);
        pB2 += __shfl_xor_sync(0xffffffffu, pB2, d);
    }
    if ((lane & 3) == 0) {
        float c0 = bh2[0], c1 = bh2[1], c2 = bh2[2];
        if (okA) {
            g_delta[r1 * 3 + 0] = tanhf(pA0 + c0);
            g_delta[r1 * 3 + 1] = tanhf(pA1 + c1);
            g_delta[r1 * 3 + 2] = tanhf(pA2 + c2);
        }
        if (okB) {
            g_delta[(r1 + 8) * 3 + 0] = tanhf(pB0 + c0);
            g_delta[(r1 + 8) * 3 + 1] = tanhf(pB1 + c1);
            g_delta[(r1 + 8) * 3 + 2] = tanhf(pB2 + c2);
        }
    }
}

// ---------------- agg: segmented max-gather of half2 y ----------------
__global__ void agg_kernel(int N) {
    int warp = (blockIdx.x * blockDim.x + threadIdx.x) >> 5;
    int lane = threadIdx.x & 31;
    if (warp >= N) return;
    int cw = lane * 2;
    int p0 = g_off[warp], p1 = g_off[warp + 1];
    float4 acc = make_float4(-INFINITY, -INFINITY, -INFINITY, -INFINITY);
    int p = p0;
    for (; p + 4 <= p1; p += 4) {
        int s0 = g_esrc[p + 0];
        int s1 = g_esrc[p + 1];
        int s2 = g_esrc[p + 2];
        int s3 = g_esrc[p + 3];
        uint2 u0 = *(const uint2*)&g_yh[(size_t)s0 * 64 + cw];
        uint2 u1 = *(const uint2*)&g_yh[(size_t)s1 * 64 + cw];
        uint2 u2 = *(const uint2*)&g_yh[(size_t)s2 * 64 + cw];
        uint2 u3 = *(const uint2*)&g_yh[(size_t)s3 * 64 + cw];
        float2 a0 = __half22float2(*(__half2*)&u0.x), b0 = __half22float2(*(__half2*)&u0.y);
        float2 a1 = __half22float2(*(__half2*)&u1.x), b1 = __half22float2(*(__half2*)&u1.y);
        float2 a2 = __half22float2(*(__half2*)&u2.x), b2 = __half22float2(*(__half2*)&u2.y);
        float2 a3 = __half22float2(*(__half2*)&u3.x), b3 = __half22float2(*(__half2*)&u3.y);
        acc.x = fmaxf(fmaxf(fmaxf(acc.x, a0.x), fmaxf(a1.x, a2.x)), a3.x);
        acc.y = fmaxf(fmaxf(fmaxf(acc.y, a0.y), fmaxf(a1.y, a2.y)), a3.y);
        acc.z = fmaxf(fmaxf(fmaxf(acc.z, b0.x), fmaxf(b1.x, b2.x)), b3.x);
        acc.w = fmaxf(fmaxf(fmaxf(acc.w, b0.y), fmaxf(b1.y, b2.y)), b3.y);
    }
    for (; p < p1; ++p) {
        int s = g_esrc[p];
        uint2 u = *(const uint2*)&g_yh[(size_t)s * 64 + cw];
        float2 a = __half22float2(*(__half2*)&u.x);
        float2 b = __half22float2(*(__half2*)&u.y);
        acc.x = fmaxf(acc.x, a.x);
        acc.y = fmaxf(acc.y, a.y);
        acc.z = fmaxf(acc.z, b.x);
        acc.w = fmaxf(acc.w, b.y);
    }
    *(float4*)&g_mx[(size_t)warp * 128 + lane * 4] = acc;
}

// ---------------- out = lrelu(agg@Wg1+bg1)@Wg2 + bg2 + x ----------------
#define MMA_SMEM_O (32768 * 2 + 34816 * 2 + 512 + 512 + 1536)
__global__ __launch_bounds__(256, 1)
void out_mma_kernel(const float* __restrict__ b1, const float* __restrict__ b2,
                    const float* __restrict__ X, const float* __restrict__ pos,
                    const float* __restrict__ Wf, float* __restrict__ O, int M) {
    extern __shared__ char smx[];
    unsigned int* Bh = (unsigned int*)smx;
    unsigned int* Bl = (unsigned int*)(smx + 32768);
    char* Ah = smx + 65536;
    char* Al = smx + 65536 + 34816;
    float* sb1 = (float*)(smx + 65536 + 69632);
    float* sb2 = (float*)(smx + 65536 + 69632 + 512);
    float* sWf = (float*)(smx + 65536 + 69632 + 1024);
    int tid = threadIdx.x, lane = tid & 31, warp = tid >> 5;
    int row0 = blockIdx.x * 128;
    int gr  = lane >> 2;
    int cc2 = (lane & 3) * 2;

    stage_B(g_bfh[2], g_bfl[2], Bh, Bl, tid);
    if (tid < 128) sb1[tid] = b1[tid];
    else if (tid < 256) sb2[tid - 128] = b2[tid - 128];
    if (tid < 96) *(float4*)&sWf[tid * 4] = *(const float4*)&Wf[tid * 4];
    __syncthreads();

    // stage A = lrelu(mx + c_d), split hi/lo
    #pragma unroll
    for (int it = 0; it < 16; it++) {
        int idx = it * 256 + tid;
        int r  = idx >> 5;
        int c4 = (idx & 31) * 4;
        int row = row0 + r;
        float4 v = make_float4(0.f, 0.f, 0.f, 0.f);
        if (row < M) {
            float4 t = *(const float4*)&g_mx[(size_t)row * 128 + c4];
            float dx = g_delta[row * 3 + 0] - pos[row * 3 + 0];
            float dy = g_delta[row * 3 + 1] - pos[row * 3 + 1];
            float dz = g_delta[row * 3 + 2] - pos[row * 3 + 2];
            float c0 = dx * sWf[c4 + 0] + dy * sWf[128 + c4 + 0] + dz * sWf[256 + c4 + 0];
            float c1 = dx * sWf[c4 + 1] + dy * sWf[128 + c4 + 1] + dz * sWf[256 + c4 + 1];
            float c2 = dx * sWf[c4 + 2] + dy * sWf[128 + c4 + 2] + dz * sWf[256 + c4 + 2];
            float c3 = dx * sWf[c4 + 3] + dy * sWf[128 + c4 + 3] + dz * sWf[256 + c4 + 3];
            v.x = (t.x == -INFINITY) ? 0.f : lrelu(t.x + c0);
            v.y = (t.y == -INFINITY) ? 0.f : lrelu(t.y + c1);
            v.z = (t.z == -INFINITY) ? 0.f : lrelu(t.z + c2);
            v.w = (t.w == -INFINITY) ? 0.f : lrelu(t.w + c3);
        }
        unsigned int h01 = pack_bf2(v.x, v.y);
        unsigned int h23 = pack_bf2(v.z, v.w);
        float hf0 = __uint_as_float(h01 << 16);
        float hf1 = __uint_as_float(h01 & 0xFFFF0000u);
        float hf2 = __uint_as_float(h23 << 16);
        float hf3 = __uint_as_float(h23 & 0xFFFF0000u);
        unsigned int l01 = pack_bf2(v.x - hf0, v.y - hf1);
        unsigned int l23 = pack_bf2(v.z - hf2, v.w - hf3);
        *(uint2*)(Ah + r * APITCH + c4 * 2) = make_uint2(h01, h23);
        *(uint2*)(Al + r * APITCH + c4 * 2) = make_uint2(l01, l23);
    }
    __syncthreads();

    float acc[16][4];
    #pragma unroll
    for (int j = 0; j < 16; j++)
        #pragma unroll
        for (int q = 0; q < 4; q++) acc[j][q] = 0.f;

    mma_mainloop(Ah, Al, Bh, Bl, acc, lane, warp);
    __syncthreads();

    // t = lrelu(acc + bg1) back into A tiles; restage B = Wg2
    {
        int rlA = warp * 16 + gr;
        #pragma unroll
        for (int j = 0; j < 16; j++) {
            int col = j * 8 + cc2;
            float b0 = sb1[col], b1v = sb1[col + 1];
            float v0 = lrelu(acc[j][0] + b0);
            float v1 = lrelu(acc[j][1] + b1v);
            float v2 = lrelu(acc[j][2] + b0);
            float v3 = lrelu(acc[j][3] + b1v);
            unsigned int hA = pack_bf2(v0, v1);
            unsigned int hB = pack_bf2(v2, v3);
            float hf0 = __uint_as_float(hA << 16);
            float hf1 = __uint_as_float(hA & 0xFFFF0000u);
            float hf2 = __uint_as_float(hB << 16);
            float hf3 = __uint_as_float(hB & 0xFFFF0000u);
            unsigned int lA = pack_bf2(v0 - hf0, v1 - hf1);
            unsigned int lB = pack_bf2(v2 - hf2, v3 - hf3);
            *(unsigned int*)(Ah + rlA * APITCH + col * 2) = hA;
            *(unsigned int*)(Al + rlA * APITCH + col * 2) = lA;
            *(unsigned int*)(Ah + (rlA + 8) * APITCH + col * 2) = hB;
            *(unsigned int*)(Al + (rlA + 8) * APITCH + col * 2) = lB;
        }
    }
    stage_B(g_bfh[3], g_bfl[3], Bh, Bl, tid);
    __syncthreads();

    #pragma unroll
    for (int j = 0; j < 16; j++)
        #pragma unroll
        for (int q = 0; q < 4; q++) acc[j][q] = 0.f;

    mma_mainloop(Ah, Al, Bh, Bl, acc, lane, warp);

    int r1 = row0 + warp * 16 + gr;
    #pragma unroll
    for (int j = 0; j < 16; j++) {
        int col = j * 8 + cc2;
        float b0 = sb2[col], b1v = sb2[col + 1];
        if (r1 < M) {
            float2 rx = *(const float2*)&X[(size_t)r1 * 128 + col];
            *(float2*)&O[(size_t)r1 * 128 + col] =
                make_float2(acc[j][0] + b0 + rx.x, acc[j][1] + b1v + rx.y);
        }
        if (r1 + 8 < M) {
            float2 rx = *(const float2*)&X[(size_t)(r1 + 8) * 128 + col];
            *(float2*)&O[(size_t)(r1 + 8) * 128 + col] =
                make_float2(acc[j][2] + b0 + rx.x, acc[j][3] + b1v + rx.y);
        }
    }
}

// ---------------- launch ----------------
extern "C" void kernel_launch(void* const* d_in, const int* in_sizes, int n_in,
                              void* d_out, int out_size) {
    const float* x   = (const float*)d_in[0];
    const float* pos = (const float*)d_in[1];
    const void*  ei  = d_in[2];
    const float* Wh1 = (const float*)d_in[3];
    const float* bh1 = (const float*)d_in[4];
    const float* Wh2 = (const float*)d_in[5];
    const float* bh2 = (const float*)d_in[6];
    const float* Wf  = (const float*)d_in[7];
    const float* bf  = (const float*)d_in[8];
    const float* Wg1 = (const float*)d_in[9];
    const float* bg1 = (const float*)d_in[10];
    const float* Wg2 = (const float*)d_in[11];
    const float* bg2 = (const float*)d_in[12];
    float* out = (float*)d_out;

    int M = in_sizes[0] / CDIM;   // 50000
    int E = in_sizes[2] / 2;      // 800000

    cudaFuncSetAttribute(xf_mma_kernel,     cudaFuncAttributeMaxDynamicSharedMemorySize, MMA_SMEM_XF);
    cudaFuncSetAttribute(hdelta_mma_kernel, cudaFuncAttributeMaxDynamicSharedMemorySize, MMA_SMEM_H);
    cudaFuncSetAttribute(out_mma_kernel,    cudaFuncAttributeMaxDynamicSharedMemorySize, MMA_SMEM_O);

    unsigned int* yhp;
    cudaGetSymbolAddress((void**)&yhp, g_yh);

    int gemm_blocks = (M + 127) / 128;
    int eblocks = (E + 255) / 256;
    int nblocks = (M + 255) / 256;
    int sblocks = (M + 1023) / 1024;
    int wblocks = (M + 7) / 8;

    static cudaStream_t s_side = nullptr;
    static cudaEvent_t  s_e0 = nullptr, s_e1 = nullptr;
    if (s_side == nullptr) {
        cudaStreamCreateWithFlags(&s_side, cudaStreamNonBlocking);
        cudaEventCreateWithFlags(&s_e0, cudaEventDisableTiming);
        cudaEventCreateWithFlags(&s_e1, cudaEventDisableTiming);
    }

    // main: weight prep
    prep_w_kernel<<<dim3(16, 4), 256>>>(Wh1, Wf + 3 * 128, Wg1, Wg2);
    cudaEventRecord(s_e0, 0);

    // side branch: CSR build (hidden under xf + hdelta)
    cudaStreamWaitEvent(s_side, s_e0, 0);
    detect_kernel<<<1, 32, 0, s_side>>>((const unsigned int*)ei, E);
    zero_cnt_kernel<<<nblocks, 256, 0, s_side>>>(M);
    convert_hist_kernel<<<eblocks, 256, 0, s_side>>>(ei, E);
    scanA_kernel<<<sblocks, 1024, 0, s_side>>>(M);
    scanB_kernel<<<1, 64, 0, s_side>>>(sblocks);
    scanC_kernel<<<sblocks, 1024, 0, s_side>>>(M);
    scatter_kernel<<<eblocks, 256, 0, s_side>>>(E);
    cudaEventRecord(s_e1, s_side);

    // main: y GEMM, then hdelta (fills CSR wait), then max-gather, then out
    xf_mma_kernel<<<gemm_blocks, 256, MMA_SMEM_XF>>>(x, bf, pos, Wf, yhp, M);
    hdelta_mma_kernel<<<gemm_blocks, 256, MMA_SMEM_H>>>(x, bh1, Wh2, bh2, M);
    cudaStreamWaitEvent(0, s_e1, 0);
    agg_kernel<<<wblocks, 256>>>(M);
    out_mma_kernel<<<gemm_blocks, 256, MMA_SMEM_O>>>(bg1, bg2, x, pos, Wf, out, M);
}

// round 15
// speedup vs baseline: 1.2776x; 1.1123x over previous
#include <cuda_runtime.h>
#include <cuda_fp16.h>
#include <math.h>
#include <stdint.h>

#define NMAX 50000
#define EMAX 800000
#define CDIM 128

// ---------------- device scratch ----------------
__device__ int   g_is64;
__device__ unsigned int g_yh[(size_t)NMAX * 64];   // y as half2
__device__ float g_mx [(size_t)NMAX * CDIM];       // segmented max of y (-inf if empty)
__device__ float g_t  [(size_t)NMAX * CDIM];       // t = lrelu(agg@Wg1+bg1)
__device__ float g_delta[(size_t)NMAX * 3];
__device__ int   g_src [EMAX];
__device__ int   g_dst [EMAX];
__device__ int   g_esrc[EMAX];
__device__ int   g_cnt [NMAX];
__device__ int   g_cur [NMAX];
__device__ int   g_off [NMAX + 1];
__device__ int   g_bsum[64];
__device__ int   g_bpre[64];
// weights pre-split bf16 hi/lo in mma fragment order: 0=Wh1 1=WfX 2=Wg1 3=Wg2
__device__ unsigned int g_bfh[4][8192];
__device__ unsigned int g_bfl[4][8192];

// ---------------- helpers ----------------
__device__ __forceinline__ float lrelu(float v) { return (v > 0.f) ? v : 0.01f * v; }
__device__ __forceinline__ unsigned int pack_bf2(float e0, float e1) {
    unsigned int r;
    asm("cvt.rn.bf16x2.f32 %0, %1, %2;" : "=r"(r) : "f"(e1), "f"(e0));
    return r;
}
__device__ __forceinline__ void mma_bf16(float acc[4],
                                         unsigned int a0, unsigned int a1, unsigned int a2, unsigned int a3,
                                         unsigned int b0, unsigned int b1) {
    asm("mma.sync.aligned.m16n8k16.row.col.f32.bf16.bf16.f32 "
        "{%0,%1,%2,%3}, {%4,%5,%6,%7}, {%8,%9}, {%0,%1,%2,%3};"
        : "+f"(acc[0]), "+f"(acc[1]), "+f"(acc[2]), "+f"(acc[3])
        : "r"(a0), "r"(a1), "r"(a2), "r"(a3), "r"(b0), "r"(b1));
}

// ---------------- dtype detection ----------------
__global__ void detect_kernel(const unsigned int* __restrict__ w, int E) {
    int nz = 0;
    int lim = 2 * E;
    for (int i = threadIdx.x; i < 256; i += 32) {
        int wi = 2 * i + 1;
        if (wi < lim) nz |= (w[wi] != 0u);
    }
    nz = __any_sync(0xffffffffu, nz);
    if (threadIdx.x == 0) g_is64 = nz ? 0 : 1;
}

__global__ void zero_cnt_kernel(int n) {
    int i = blockIdx.x * blockDim.x + threadIdx.x;
    if (i < n) { g_cnt[i] = 0; g_cur[i] = 0; }
}

__global__ void convert_hist_kernel(const void* __restrict__ ei, int E) {
    int i = blockIdx.x * blockDim.x + threadIdx.x;
    if (i >= E) return;
    int s, d;
    if (g_is64) {
        const long long* p = (const long long*)ei;
        s = (int)p[i];
        d = (int)p[E + i];
    } else {
        const int* p = (const int*)ei;
        s = p[i];
        d = p[E + i];
    }
    g_src[i] = s;
    g_dst[i] = d;
    atomicAdd(&g_cnt[d], 1);
}

// ---------------- hierarchical scan ----------------
__global__ void scanA_kernel(int n) {
    __shared__ int wsum[32];
    int tid = threadIdx.x, lane = tid & 31, wid = tid >> 5;
    int i = blockIdx.x * 1024 + tid;
    int v = (i < n) ? g_cnt[i] : 0;
    int x = v;
    #pragma unroll
    for (int d = 1; d < 32; d <<= 1) {
        int t = __shfl_up_sync(0xffffffffu, x, d);
        if (lane >= d) x += t;
    }
    if (lane == 31) wsum[wid] = x;
    __syncthreads();
    if (wid == 0) {
        int s = wsum[lane];
        #pragma unroll
        for (int d = 1; d < 32; d <<= 1) {
            int t = __shfl_up_sync(0xffffffffu, s, d);
            if (lane >= d) s += t;
        }
        wsum[lane] = s;
    }
    __syncthreads();
    if (wid > 0) x += wsum[wid - 1];
    if (i < n) g_off[i + 1] = x;
    if (tid == 1023) g_bsum[blockIdx.x] = x;
}

__global__ void scanB_kernel(int nb) {
    __shared__ int ws[2];
    int t = threadIdx.x, lane = t & 31, w = t >> 5;
    int v = (t < nb) ? g_bsum[t] : 0;
    int x = v;
    #pragma unroll
    for (int d = 1; d < 32; d <<= 1) {
        int u = __shfl_up_sync(0xffffffffu, x, d);
        if (lane >= d) x += u;
    }
    if (lane == 31) ws[w] = x;
    __syncthreads();
    if (w == 1) x += ws[0];
    if (t < nb) g_bpre[t] = x - v;
}

__global__ void scanC_kernel(int n) {
    int i = blockIdx.x * 1024 + threadIdx.x;
    int add = g_bpre[blockIdx.x];
    if (i < n) g_off[i + 1] += add;
    if (i == 0) g_off[0] = 0;
}

__global__ void scatter_kernel(int E) {
    int i = blockIdx.x * blockDim.x + threadIdx.x;
    if (i >= E) return;
    int d = g_dst[i];
    int p = g_off[d] + atomicAdd(&g_cur[d], 1);
    g_esrc[p] = g_src[i];
}

// ---------------- weight prep ----------------
__global__ void prep_w_kernel(const float* __restrict__ Wh1, const float* __restrict__ WfX,
                              const float* __restrict__ Wg1, const float* __restrict__ Wg2) {
    const float* W = (blockIdx.y == 0) ? Wh1 : (blockIdx.y == 1) ? WfX :
                     (blockIdx.y == 2) ? Wg1 : Wg2;
    int idx = blockIdx.x * 256 + threadIdx.x;
    if (idx >= 4096) return;
    int t  = idx & 31;
    int j  = (idx >> 5) & 15;
    int ks = idx >> 9;
    int n  = j * 8 + (t >> 2);
    int k1 = ks * 16 + 2 * (t & 3);
    float w00 = W[k1 * 128 + n],       w01 = W[(k1 + 1) * 128 + n];
    float w10 = W[(k1 + 8) * 128 + n], w11 = W[(k1 + 9) * 128 + n];
    unsigned int h0 = pack_bf2(w00, w01);
    unsigned int h1 = pack_bf2(w10, w11);
    float hf00 = __uint_as_float(h0 << 16);
    float hf01 = __uint_as_float(h0 & 0xFFFF0000u);
    float hf10 = __uint_as_float(h1 << 16);
    float hf11 = __uint_as_float(h1 & 0xFFFF0000u);
    unsigned int l0 = pack_bf2(w00 - hf00, w01 - hf01);
    unsigned int l1 = pack_bf2(w10 - hf10, w11 - hf11);
    g_bfh[blockIdx.y][idx * 2 + 0] = h0;
    g_bfh[blockIdx.y][idx * 2 + 1] = h1;
    g_bfl[blockIdx.y][idx * 2 + 0] = l0;
    g_bfl[blockIdx.y][idx * 2 + 1] = l1;
}

// ---------------- shared mma building blocks ----------------
__device__ __forceinline__ void stage_B(const unsigned int* __restrict__ fh,
                                        const unsigned int* __restrict__ fl,
                                        unsigned int* Bh, unsigned int* Bl, int tid) {
    #pragma unroll
    for (int i = 0; i < 8; i++) {
        int idx = i * 256 + tid;
        ((uint4*)Bh)[idx] = ((const uint4*)fh)[idx];
        ((uint4*)Bl)[idx] = ((const uint4*)fl)[idx];
    }
}

__device__ __forceinline__ void split2(float2 v, unsigned int& h, unsigned int& l) {
    h = pack_bf2(v.x, v.y);
    float hf0 = __uint_as_float(h << 16);
    float hf1 = __uint_as_float(h & 0xFFFF0000u);
    l = pack_bf2(v.x - hf0, v.y - hf1);
}

// inner jb-loop over B fragments given one ks-step of A fragments
__device__ __forceinline__ void mma_jb(const unsigned int* Bh, const unsigned int* Bl,
                                       float acc[16][4], int lane, int ks,
                                       unsigned int ah0, unsigned int ah1, unsigned int ah2, unsigned int ah3,
                                       unsigned int al0, unsigned int al1, unsigned int al2, unsigned int al3) {
    #pragma unroll
    for (int jb = 0; jb < 4; jb++) {
        unsigned int bh[4][2], bl[4][2];
        #pragma unroll
        for (int q = 0; q < 4; q++) {
            int slot = ((ks * 16 + jb * 4 + q) * 32 + lane) * 2;
            uint2 t1 = *(const uint2*)&Bh[slot];
            uint2 t2 = *(const uint2*)&Bl[slot];
            bh[q][0] = t1.x; bh[q][1] = t1.y;
            bl[q][0] = t2.x; bl[q][1] = t2.y;
        }
        #pragma unroll
        for (int q = 0; q < 4; q++)
            mma_bf16(acc[jb * 4 + q], ah0, ah1, ah2, ah3, bh[q][0], bh[q][1]);
        #pragma unroll
        for (int q = 0; q < 4; q++)
            mma_bf16(acc[jb * 4 + q], ah0, ah1, ah2, ah3, bl[q][0], bl[q][1]);
        #pragma unroll
        for (int q = 0; q < 4; q++)
            mma_bf16(acc[jb * 4 + q], al0, al1, al2, al3, bh[q][0], bh[q][1]);
    }
}

// register-A mainloop: A fragments loaded directly from gmem (fp32 row-major [*,128])
__device__ __forceinline__ void mma_mainloop_regA(
    const float* __restrict__ rowA, const float* __restrict__ rowB, bool okA, bool okB,
    const unsigned int* Bh, const unsigned int* Bl,
    float acc[16][4], int lane)
{
    int cc2 = (lane & 3) * 2;
    #pragma unroll
    for (int ks = 0; ks < 8; ks++) {
        int k0 = ks * 16 + cc2;
        float2 vA0 = make_float2(0.f, 0.f), vA1 = vA0, vB0 = vA0, vB1 = vA0;
        if (okA) { vA0 = *(const float2*)&rowA[k0]; vA1 = *(const float2*)&rowA[k0 + 8]; }
        if (okB) { vB0 = *(const float2*)&rowB[k0]; vB1 = *(const float2*)&rowB[k0 + 8]; }
        unsigned int ah0, ah1, ah2, ah3, al0, al1, al2, al3;
        split2(vA0, ah0, al0);
        split2(vB0, ah1, al1);
        split2(vA1, ah2, al2);
        split2(vB1, ah3, al3);
        mma_jb(Bh, Bl, acc, lane, ks, ah0, ah1, ah2, ah3, al0, al1, al2, al3);
    }
}

// ---------------- y = x @ WfX + bf + pos·Wf_rel  (half2); occ 2 ----------------
#define MMA_SMEM_XF (32768 * 2 + 512 + 1536)
__global__ __launch_bounds__(256, 2)
void xf_mma_kernel(const float* __restrict__ A, const float* __restrict__ bias,
                   const float* __restrict__ pos, const float* __restrict__ Wf,
                   unsigned int* __restrict__ O, int M) {
    extern __shared__ char smx[];
    unsigned int* Bh = (unsigned int*)smx;
    unsigned int* Bl = (unsigned int*)(smx + 32768);
    float* sbias = (float*)(smx + 65536);
    float* sWf   = (float*)(smx + 65536 + 512);
    int tid = threadIdx.x, lane = tid & 31, warp = tid >> 5;
    int row0 = blockIdx.x * 128;

    stage_B(g_bfh[1], g_bfl[1], Bh, Bl, tid);
    if (tid < 128) sbias[tid] = bias[tid];
    if (tid >= 128 && tid < 224) *(float4*)&sWf[(tid - 128) * 4] = *(const float4*)&Wf[(tid - 128) * 4];
    __syncthreads();

    int gr  = lane >> 2;
    int cc2 = (lane & 3) * 2;
    int r1 = row0 + warp * 16 + gr;
    bool okA = r1 < M, okB = (r1 + 8) < M;
    const float* rowA = A + (size_t)r1 * 128;
    const float* rowB = A + (size_t)(r1 + 8) * 128;

    float acc[16][4];
    #pragma unroll
    for (int j = 0; j < 16; j++)
        #pragma unroll
        for (int q = 0; q < 4; q++) acc[j][q] = 0.f;

    mma_mainloop_regA(rowA, rowB, okA, okB, Bh, Bl, acc, lane);

    float pAx = 0.f, pAy = 0.f, pAz = 0.f, pBx = 0.f, pBy = 0.f, pBz = 0.f;
    if (okA) { pAx = pos[r1 * 3]; pAy = pos[r1 * 3 + 1]; pAz = pos[r1 * 3 + 2]; }
    if (okB) { pBx = pos[(r1 + 8) * 3]; pBy = pos[(r1 + 8) * 3 + 1]; pBz = pos[(r1 + 8) * 3 + 2]; }
    #pragma unroll
    for (int j = 0; j < 16; j++) {
        int col = j * 8 + cc2;
        float b0 = sbias[col], b1 = sbias[col + 1];
        float w00 = sWf[col], w10 = sWf[128 + col], w20 = sWf[256 + col];
        float w01 = sWf[col + 1], w11 = sWf[128 + col + 1], w21 = sWf[256 + col + 1];
        if (okA) {
            float y0 = acc[j][0] + b0 + pAx * w00 + pAy * w10 + pAz * w20;
            float y1 = acc[j][1] + b1 + pAx * w01 + pAy * w11 + pAz * w21;
            __half2 h = __floats2half2_rn(y0, y1);
            O[(size_t)r1 * 64 + (col >> 1)] = *(unsigned int*)&h;
        }
        if (okB) {
            float y2 = acc[j][2] + b0 + pBx * w00 + pBy * w10 + pBz * w20;
            float y3 = acc[j][3] + b1 + pBx * w01 + pBy * w11 + pBz * w21;
            __half2 h = __floats2half2_rn(y2, y3);
            O[(size_t)(r1 + 8) * 64 + (col >> 1)] = *(unsigned int*)&h;
        }
    }
}

// ---------------- delta = tanh(lrelu(x@Wh1+bh1) @ Wh2 + bh2); occ 2 ----------------
#define MMA_SMEM_H (32768 * 2 + 512 + 1536)
__global__ __launch_bounds__(256, 2)
void hdelta_mma_kernel(const float* __restrict__ A, const float* __restrict__ bias,
                       const float* __restrict__ Wh2, const float* __restrict__ bh2, int M) {
    extern __shared__ char smx[];
    unsigned int* Bh = (unsigned int*)smx;
    unsigned int* Bl = (unsigned int*)(smx + 32768);
    float* sbias = (float*)(smx + 65536);
    float* sW2   = (float*)(smx + 65536 + 512);
    int tid = threadIdx.x, lane = tid & 31, warp = tid >> 5;
    int row0 = blockIdx.x * 128;

    stage_B(g_bfh[0], g_bfl[0], Bh, Bl, tid);
    if (tid < 128) sbias[tid] = bias[tid];
    if (tid >= 128 && tid < 224) *(float4*)&sW2[(tid - 128) * 4] = *(const float4*)&Wh2[(tid - 128) * 4];
    __syncthreads();

    int gr  = lane >> 2;
    int cc2 = (lane & 3) * 2;
    int r1 = row0 + warp * 16 + gr;
    bool okA = r1 < M, okB = (r1 + 8) < M;
    const float* rowA = A + (size_t)r1 * 128;
    const float* rowB = A + (size_t)(r1 + 8) * 128;

    float acc[16][4];
    #pragma unroll
    for (int j = 0; j < 16; j++)
        #pragma unroll
        for (int q = 0; q < 4; q++) acc[j][q] = 0.f;

    mma_mainloop_regA(rowA, rowB, okA, okB, Bh, Bl, acc, lane);

    float pA0 = 0.f, pA1 = 0.f, pA2 = 0.f;
    float pB0 = 0.f, pB1 = 0.f, pB2 = 0.f;
    #pragma unroll
    for (int j = 0; j < 16; j++) {
        int col = j * 8 + cc2;
        float b0 = sbias[col], b1 = sbias[col + 1];
        float v0 = lrelu(acc[j][0] + b0);
        float v1 = lrelu(acc[j][1] + b1);
        float v2 = lrelu(acc[j][2] + b0);
        float v3 = lrelu(acc[j][3] + b1);
        float w00 = sW2[col * 3 + 0], w01 = sW2[col * 3 + 1], w02 = sW2[col * 3 + 2];
        float w10 = sW2[(col + 1) * 3 + 0], w11 = sW2[(col + 1) * 3 + 1], w12 = sW2[(col + 1) * 3 + 2];
        pA0 += v0 * w00 + v1 * w10;
        pA1 += v0 * w01 + v1 * w11;
        pA2 += v0 * w02 + v1 * w12;
        pB0 += v2 * w00 + v3 * w10;
        pB1 += v2 * w01 + v3 * w11;
        pB2 += v2 * w02 + v3 * w12;
    }
    #pragma unroll
    for (int d = 1; d < 4; d <<= 1) {
        pA0 += __shfl_xor_sync(0xffffffffu, pA0, d);
        pA1 += __shfl_xor_sync(0xffffffffu, pA1, d);
        pA2 += __shfl_xor_sync(0xffffffffu, pA2, d);
        pB0 += __shfl_xor_sync(0xffffffffu, pB0, d);
        pB1 += __shfl_xor_sync(0xffffffffu, pB1, d);
        pB2 += __shfl_xor_sync(0xffffffffu, pB2, d);
    }
    if ((lane & 3) == 0) {
        float c0 = bh2[0], c1 = bh2[1], c2 = bh2[2];
        if (okA) {
            g_delta[r1 * 3 + 0] = tanhf(pA0 + c0);
            g_delta[r1 * 3 + 1] = tanhf(pA1 + c1);
            g_delta[r1 * 3 + 2] = tanhf(pA2 + c2);
        }
        if (okB) {
            g_delta[(r1 + 8) * 3 + 0] = tanhf(pB0 + c0);
            g_delta[(r1 + 8) * 3 + 1] = tanhf(pB1 + c1);
            g_delta[(r1 + 8) * 3 + 2] = tanhf(pB2 + c2);
        }
    }
}

// ---------------- agg: segmented max-gather of half2 y ----------------
__global__ void agg_kernel(int N) {
    int warp = (blockIdx.x * blockDim.x + threadIdx.x) >> 5;
    int lane = threadIdx.x & 31;
    if (warp >= N) return;
    int cw = lane * 2;
    int p0 = g_off[warp], p1 = g_off[warp + 1];
    float4 acc = make_float4(-INFINITY, -INFINITY, -INFINITY, -INFINITY);
    int p = p0;
    for (; p + 4 <= p1; p += 4) {
        int s0 = g_esrc[p + 0];
        int s1 = g_esrc[p + 1];
        int s2 = g_esrc[p + 2];
        int s3 = g_esrc[p + 3];
        uint2 u0 = *(const uint2*)&g_yh[(size_t)s0 * 64 + cw];
        uint2 u1 = *(const uint2*)&g_yh[(size_t)s1 * 64 + cw];
        uint2 u2 = *(const uint2*)&g_yh[(size_t)s2 * 64 + cw];
        uint2 u3 = *(const uint2*)&g_yh[(size_t)s3 * 64 + cw];
        float2 a0 = __half22float2(*(__half2*)&u0.x), b0 = __half22float2(*(__half2*)&u0.y);
        float2 a1 = __half22float2(*(__half2*)&u1.x), b1 = __half22float2(*(__half2*)&u1.y);
        float2 a2 = __half22float2(*(__half2*)&u2.x), b2 = __half22float2(*(__half2*)&u2.y);
        float2 a3 = __half22float2(*(__half2*)&u3.x), b3 = __half22float2(*(__half2*)&u3.y);
        acc.x = fmaxf(fmaxf(fmaxf(acc.x, a0.x), fmaxf(a1.x, a2.x)), a3.x);
        acc.y = fmaxf(fmaxf(fmaxf(acc.y, a0.y), fmaxf(a1.y, a2.y)), a3.y);
        acc.z = fmaxf(fmaxf(fmaxf(acc.z, b0.x), fmaxf(b1.x, b2.x)), b3.x);
        acc.w = fmaxf(fmaxf(fmaxf(acc.w, b0.y), fmaxf(b1.y, b2.y)), b3.y);
    }
    for (; p < p1; ++p) {
        int s = g_esrc[p];
        uint2 u = *(const uint2*)&g_yh[(size_t)s * 64 + cw];
        float2 a = __half22float2(*(__half2*)&u.x);
        float2 b = __half22float2(*(__half2*)&u.y);
        acc.x = fmaxf(acc.x, a.x);
        acc.y = fmaxf(acc.y, a.y);
        acc.z = fmaxf(acc.z, b.x);
        acc.w = fmaxf(acc.w, b.y);
    }
    *(float4*)&g_mx[(size_t)warp * 128 + lane * 4] = acc;
}

// ---------------- out1: t = lrelu( lrelu(mx + c_d) @ Wg1 + bg1 ); occ 2, reg-A ----------------
// A fragments computed in-register: a[r][k] = (mx==-inf) ? 0 : lrelu(mx[r][k] + c_d(r,k))
#define MMA_SMEM_O1 (32768 * 2 + 512 + 1536)
__global__ __launch_bounds__(256, 2)
void out1_mma_kernel(const float* __restrict__ b1, const float* __restrict__ pos,
                     const float* __restrict__ Wf, float* __restrict__ T, int M) {
    extern __shared__ char smx[];
    unsigned int* Bh = (unsigned int*)smx;
    unsigned int* Bl = (unsigned int*)(smx + 32768);
    float* sb1 = (float*)(smx + 65536);
    float* sWf = (float*)(smx + 65536 + 512);
    int tid = threadIdx.x, lane = tid & 31, warp = tid >> 5;
    int row0 = blockIdx.x * 128;
    int gr  = lane >> 2;
    int cc2 = (lane & 3) * 2;

    stage_B(g_bfh[2], g_bfl[2], Bh, Bl, tid);
    if (tid < 128) sb1[tid] = b1[tid];
    if (tid >= 128 && tid < 224) *(float4*)&sWf[(tid - 128) * 4] = *(const float4*)&Wf[(tid - 128) * 4];
    __syncthreads();

    int r1 = row0 + warp * 16 + gr;
    bool okA = r1 < M, okB = (r1 + 8) < M;
    const float* rowA = g_mx + (size_t)r1 * 128;
    const float* rowB = g_mx + (size_t)(r1 + 8) * 128;
    float dAx = 0.f, dAy = 0.f, dAz = 0.f, dBx = 0.f, dBy = 0.f, dBz = 0.f;
    if (okA) {
        dAx = g_delta[r1 * 3 + 0] - pos[r1 * 3 + 0];
        dAy = g_delta[r1 * 3 + 1] - pos[r1 * 3 + 1];
        dAz = g_delta[r1 * 3 + 2] - pos[r1 * 3 + 2];
    }
    if (okB) {
        dBx = g_delta[(r1 + 8) * 3 + 0] - pos[(r1 + 8) * 3 + 0];
        dBy = g_delta[(r1 + 8) * 3 + 1] - pos[(r1 + 8) * 3 + 1];
        dBz = g_delta[(r1 + 8) * 3 + 2] - pos[(r1 + 8) * 3 + 2];
    }

    float acc[16][4];
    #pragma unroll
    for (int j = 0; j < 16; j++)
        #pragma unroll
        for (int q = 0; q < 4; q++) acc[j][q] = 0.f;

    #pragma unroll
    for (int ks = 0; ks < 8; ks++) {
        int k0 = ks * 16 + cc2;
        float2 vA0 = make_float2(0.f, 0.f), vA1 = vA0, vB0 = vA0, vB1 = vA0;
        // c_d for cols k0,k0+1 and k0+8,k0+9
        float c00 = dAx * sWf[k0]     + dAy * sWf[128 + k0]     + dAz * sWf[256 + k0];
        float c01 = dAx * sWf[k0 + 1] + dAy * sWf[128 + k0 + 1] + dAz * sWf[256 + k0 + 1];
        float c08 = dAx * sWf[k0 + 8] + dAy * sWf[128 + k0 + 8] + dAz * sWf[256 + k0 + 8];
        float c09 = dAx * sWf[k0 + 9] + dAy * sWf[128 + k0 + 9] + dAz * sWf[256 + k0 + 9];
        float e00 = dBx * sWf[k0]     + dBy * sWf[128 + k0]     + dBz * sWf[256 + k0];
        float e01 = dBx * sWf[k0 + 1] + dBy * sWf[128 + k0 + 1] + dBz * sWf[256 + k0 + 1];
        float e08 = dBx * sWf[k0 + 8] + dBy * sWf[128 + k0 + 8] + dBz * sWf[256 + k0 + 8];
        float e09 = dBx * sWf[k0 + 9] + dBy * sWf[128 + k0 + 9] + dBz * sWf[256 + k0 + 9];
        if (okA) {
            float2 m0 = *(const float2*)&rowA[k0];
            float2 m1 = *(const float2*)&rowA[k0 + 8];
            vA0.x = (m0.x == -INFINITY) ? 0.f : lrelu(m0.x + c00);
            vA0.y = (m0.y == -INFINITY) ? 0.f : lrelu(m0.y + c01);
            vA1.x = (m1.x == -INFINITY) ? 0.f : lrelu(m1.x + c08);
            vA1.y = (m1.y == -INFINITY) ? 0.f : lrelu(m1.y + c09);
        }
        if (okB) {
            float2 m0 = *(const float2*)&rowB[k0];
            float2 m1 = *(const float2*)&rowB[k0 + 8];
            vB0.x = (m0.x == -INFINITY) ? 0.f : lrelu(m0.x + e00);
            vB0.y = (m0.y == -INFINITY) ? 0.f : lrelu(m0.y + e01);
            vB1.x = (m1.x == -INFINITY) ? 0.f : lrelu(m1.x + e08);
            vB1.y = (m1.y == -INFINITY) ? 0.f : lrelu(m1.y + e09);
        }
        unsigned int ah0, ah1, ah2, ah3, al0, al1, al2, al3;
        split2(vA0, ah0, al0);
        split2(vB0, ah1, al1);
        split2(vA1, ah2, al2);
        split2(vB1, ah3, al3);
        mma_jb(Bh, Bl, acc, lane, ks, ah0, ah1, ah2, ah3, al0, al1, al2, al3);
    }

    // epilogue: t = lrelu(acc + bg1) -> g_t (fp32)
    #pragma unroll
    for (int j = 0; j < 16; j++) {
        int col = j * 8 + cc2;
        float b0 = sb1[col], b1v = sb1[col + 1];
        if (okA)
            *(float2*)&T[(size_t)r1 * 128 + col] =
                make_float2(lrelu(acc[j][0] + b0), lrelu(acc[j][1] + b1v));
        if (okB)
            *(float2*)&T[(size_t)(r1 + 8) * 128 + col] =
                make_float2(lrelu(acc[j][2] + b0), lrelu(acc[j][3] + b1v));
    }
}

// ---------------- out2: O = t @ Wg2 + bg2 + x; occ 2, reg-A ----------------
#define MMA_SMEM_O2 (32768 * 2 + 512)
__global__ __launch_bounds__(256, 2)
void out2_mma_kernel(const float* __restrict__ T, const float* __restrict__ b2,
                     const float* __restrict__ X, float* __restrict__ O, int M) {
    extern __shared__ char smx[];
    unsigned int* Bh = (unsigned int*)smx;
    unsigned int* Bl = (unsigned int*)(smx + 32768);
    float* sb2 = (float*)(smx + 65536);
    int tid = threadIdx.x, lane = tid & 31, warp = tid >> 5;
    int row0 = blockIdx.x * 128;
    int gr  = lane >> 2;
    int cc2 = (lane & 3) * 2;

    stage_B(g_bfh[3], g_bfl[3], Bh, Bl, tid);
    if (tid < 128) sb2[tid] = b2[tid];
    __syncthreads();

    int r1 = row0 + warp * 16 + gr;
    bool okA = r1 < M, okB = (r1 + 8) < M;
    const float* rowA = T + (size_t)r1 * 128;
    const float* rowB = T + (size_t)(r1 + 8) * 128;

    float acc[16][4];
    #pragma unroll
    for (int j = 0; j < 16; j++)
        #pragma unroll
        for (int q = 0; q < 4; q++) acc[j][q] = 0.f;

    mma_mainloop_regA(rowA, rowB, okA, okB, Bh, Bl, acc, lane);

    #pragma unroll
    for (int j = 0; j < 16; j++) {
        int col = j * 8 + cc2;
        float b0 = sb2[col], b1v = sb2[col + 1];
        if (okA) {
            float2 rx = *(const float2*)&X[(size_t)r1 * 128 + col];
            *(float2*)&O[(size_t)r1 * 128 + col] =
                make_float2(acc[j][0] + b0 + rx.x, acc[j][1] + b1v + rx.y);
        }
        if (okB) {
            float2 rx = *(const float2*)&X[(size_t)(r1 + 8) * 128 + col];
            *(float2*)&O[(size_t)(r1 + 8) * 128 + col] =
                make_float2(acc[j][2] + b0 + rx.x, acc[j][3] + b1v + rx.y);
        }
    }
}

// ---------------- launch ----------------
extern "C" void kernel_launch(void* const* d_in, const int* in_sizes, int n_in,
                              void* d_out, int out_size) {
    const float* x   = (const float*)d_in[0];
    const float* pos = (const float*)d_in[1];
    const void*  ei  = d_in[2];
    const float* Wh1 = (const float*)d_in[3];
    const float* bh1 = (const float*)d_in[4];
    const float* Wh2 = (const float*)d_in[5];
    const float* bh2 = (const float*)d_in[6];
    const float* Wf  = (const float*)d_in[7];
    const float* bf  = (const float*)d_in[8];
    const float* Wg1 = (const float*)d_in[9];
    const float* bg1 = (const float*)d_in[10];
    const float* Wg2 = (const float*)d_in[11];
    const float* bg2 = (const float*)d_in[12];
    float* out = (float*)d_out;

    int M = in_sizes[0] / CDIM;   // 50000
    int E = in_sizes[2] / 2;      // 800000

    cudaFuncSetAttribute(xf_mma_kernel,     cudaFuncAttributeMaxDynamicSharedMemorySize, MMA_SMEM_XF);
    cudaFuncSetAttribute(hdelta_mma_kernel, cudaFuncAttributeMaxDynamicSharedMemorySize, MMA_SMEM_H);
    cudaFuncSetAttribute(out1_mma_kernel,   cudaFuncAttributeMaxDynamicSharedMemorySize, MMA_SMEM_O1);
    cudaFuncSetAttribute(out2_mma_kernel,   cudaFuncAttributeMaxDynamicSharedMemorySize, MMA_SMEM_O2);

    unsigned int* yhp;
    float* tp;
    cudaGetSymbolAddress((void**)&yhp, g_yh);
    cudaGetSymbolAddress((void**)&tp,  g_t);

    int gemm_blocks = (M + 127) / 128;
    int eblocks = (E + 255) / 256;
    int nblocks = (M + 255) / 256;
    int sblocks = (M + 1023) / 1024;
    int wblocks = (M + 7) / 8;

    static cudaStream_t s_side = nullptr;
    static cudaEvent_t  s_e0 = nullptr, s_e1 = nullptr;
    if (s_side == nullptr) {
        cudaStreamCreateWithFlags(&s_side, cudaStreamNonBlocking);
        cudaEventCreateWithFlags(&s_e0, cudaEventDisableTiming);
        cudaEventCreateWithFlags(&s_e1, cudaEventDisableTiming);
    }

    // main: weight prep
    prep_w_kernel<<<dim3(16, 4), 256>>>(Wh1, Wf + 3 * 128, Wg1, Wg2);
    cudaEventRecord(s_e0, 0);

    // side branch: CSR build (hidden under xf + hdelta)
    cudaStreamWaitEvent(s_side, s_e0, 0);
    detect_kernel<<<1, 32, 0, s_side>>>((const unsigned int*)ei, E);
    zero_cnt_kernel<<<nblocks, 256, 0, s_side>>>(M);
    convert_hist_kernel<<<eblocks, 256, 0, s_side>>>(ei, E);
    scanA_kernel<<<sblocks, 1024, 0, s_side>>>(M);
    scanB_kernel<<<1, 64, 0, s_side>>>(sblocks);
    scanC_kernel<<<sblocks, 1024, 0, s_side>>>(M);
    scatter_kernel<<<eblocks, 256, 0, s_side>>>(E);
    cudaEventRecord(s_e1, s_side);

    // main: y GEMM, then hdelta (fills CSR wait), then max-gather, then out1/out2
    xf_mma_kernel<<<gemm_blocks, 256, MMA_SMEM_XF>>>(x, bf, pos, Wf, yhp, M);
    hdelta_mma_kernel<<<gemm_blocks, 256, MMA_SMEM_H>>>(x, bh1, Wh2, bh2, M);
    cudaStreamWaitEvent(0, s_e1, 0);
    agg_kernel<<<wblocks, 256>>>(M);
    out1_mma_kernel<<<gemm_blocks, 256, MMA_SMEM_O1>>>(bg1, pos, Wf, tp, M);
    out2_mma_kernel<<<gemm_blocks, 256, MMA_SMEM_O2>>>(tp, bg2, x, out, M);
}